// round 5
// baseline (speedup 1.0000x reference)
#include <cuda_runtime.h>

// GraphConvDown: per-edge MLP (35 -> 64 -> 64) + scatter-max onto M sampled points.
// Round 5: tensor-core main kernel (same as R4 design, which never ran due to an
// infra failure), with the contract-violating static guard removed.
// Edges counting-sorted by destination; tiles of 128 edges go through two GEMMs
// via mma.sync.m16n8k8 tf32 with 3-term split precision (rel err ~1e-6). Weights
// enter fragments once per tile instead of once per edge, removing the L1tex
// broadcast-replication bottleneck that pinned rounds 1-3 at ~1.28 ms.
//
// Output layout (float32): out[0..4M) = new_bxyz [M,4]; out[4M..4M+64M) = new_feat [M,64]

#define K1 35
#define MAXM 131072
#define MAXE 2000128
#define SCAN_BLK 1024
#define TILE 128

// ---------- static scratch ----------
__device__ int  g_cnt[MAXM];
__device__ int  g_incl[MAXM];
__device__ int  g_cursor[MAXM];
__device__ int  g_bsum[256];
__device__ int  g_btop[256];
__device__ int2 g_sorted[MAXE];     // (e_point, e_new) sorted by e_new

// ---------------------------------------------------------------------------
// Preprocessing
// ---------------------------------------------------------------------------
__global__ void k_init(const float4* __restrict__ bxyz4,
                       const int* __restrict__ sample_idx,
                       float* __restrict__ out, int M) {
    int i = blockIdx.x * blockDim.x + threadIdx.x;
    int stride = gridDim.x * blockDim.x;
    float4* ob = (float4*)out;
    for (int j = i; j < M; j += stride) {
        ob[j] = bxyz4[sample_idx[j]];
        g_cnt[j] = 0;
    }
    float4* fz = (float4*)(out + 4 * (size_t)M);
    int tot = M * 16;
    for (int j = i; j < tot; j += stride)
        fz[j] = make_float4(0.f, 0.f, 0.f, 0.f);
}

__global__ void k_hist(const int* __restrict__ e_new, int E) {
    int i = blockIdx.x * blockDim.x + threadIdx.x;
    if (i < E) atomicAdd(&g_cnt[e_new[i]], 1);
}

__global__ void k_scan1(int M) {
    __shared__ int sh[SCAN_BLK];
    int i = blockIdx.x * SCAN_BLK + threadIdx.x;
    int v = (i < M) ? g_cnt[i] : 0;
    sh[threadIdx.x] = v;
    __syncthreads();
    for (int d = 1; d < SCAN_BLK; d <<= 1) {
        int t = (threadIdx.x >= d) ? sh[threadIdx.x - d] : 0;
        __syncthreads();
        sh[threadIdx.x] += t;
        __syncthreads();
    }
    if (i < M) g_incl[i] = sh[threadIdx.x];
    if (threadIdx.x == SCAN_BLK - 1) g_bsum[blockIdx.x] = sh[SCAN_BLK - 1];
}
__global__ void k_scan2(int NB) {
    __shared__ int sh[256];
    int v = (threadIdx.x < NB) ? g_bsum[threadIdx.x] : 0;
    sh[threadIdx.x] = v;
    __syncthreads();
    for (int d = 1; d < 256; d <<= 1) {
        int t = (threadIdx.x >= d) ? sh[threadIdx.x - d] : 0;
        __syncthreads();
        sh[threadIdx.x] += t;
        __syncthreads();
    }
    g_btop[threadIdx.x] = sh[threadIdx.x] - v;
}
__global__ void k_scan3(int M) {
    int i = blockIdx.x * blockDim.x + threadIdx.x;
    if (i < M)
        g_cursor[i] = g_incl[i] - g_cnt[i] + g_btop[i >> 10];
}

__global__ void k_scatter(const int* __restrict__ e_point,
                          const int* __restrict__ e_new, int E) {
    int i = blockIdx.x * blockDim.x + threadIdx.x;
    if (i < E) {
        int m = e_new[i];
        int pos = atomicAdd(&g_cursor[m], 1);
        g_sorted[pos] = make_int2(e_point[i], m);
    }
}

// ---------------------------------------------------------------------------
// mma helpers
// ---------------------------------------------------------------------------
__device__ __forceinline__ unsigned tf32_hi(float f) {
    unsigned r;
    asm("cvt.rna.tf32.f32 %0, %1;" : "=r"(r) : "f"(f));
    return r;
}
__device__ __forceinline__ void mma_tf32(float& c0, float& c1, float& c2, float& c3,
                                         unsigned a0, unsigned a1, unsigned a2, unsigned a3,
                                         unsigned b0, unsigned b1) {
    asm volatile("mma.sync.aligned.m16n8k8.row.col.f32.tf32.tf32.f32 "
                 "{%0,%1,%2,%3}, {%4,%5,%6,%7}, {%8,%9}, {%0,%1,%2,%3};"
                 : "+f"(c0), "+f"(c1), "+f"(c2), "+f"(c3)
                 : "r"(a0), "r"(a1), "r"(a2), "r"(a3), "r"(b0), "r"(b1));
}

// SMEM layout (floats). Strides chosen conflict-free for the fragment patterns.
#define S_W1   0                    // [40][72]
#define S_W2   (S_W1 + 40 * 72)     // [64][72]
#define S_B1   (S_W2 + 64 * 72)     // [64]
#define S_B2   (S_B1 + 64)          // [64]
#define S_M    (S_B2 + 64)          // [128] ints
#define S_EF   (S_M + 128)          // [128][44]
#define S_C1   (S_EF + 128 * 44)    // [128][68]
#define S_TOT  (S_C1 + 128 * 68)    // 22208 floats = 88832 B

// ---------------------------------------------------------------------------
// Main tensor-core kernel: one block = 128 sorted edges.
// ---------------------------------------------------------------------------
__global__ __launch_bounds__(128)
void k_main_tc(const float4* __restrict__ bxyz4,
               const float4* __restrict__ feat4,
               const float*  __restrict__ W1, const float* __restrict__ b1,
               const float*  __restrict__ W2, const float* __restrict__ b2,
               const float4* __restrict__ newb4,
               int*          __restrict__ outf,
               int E)
{
    extern __shared__ float sm[];
    float* W1s = sm + S_W1;
    float* W2s = sm + S_W2;
    float* b1s = sm + S_B1;
    float* b2s = sm + S_B2;
    int*   smm = (int*)(sm + S_M);
    float* ef  = sm + S_EF;
    float* C1  = sm + S_C1;

    int tid  = threadIdx.x;
    int warp = tid >> 5;
    int lane = tid & 31;
    int g    = lane >> 2;   // groupID
    int tg   = lane & 3;    // threadID_in_group

    // ---- load weights (pad K1 35->40 with zero rows) ----
    for (int i = tid; i < 40 * 64; i += 128) {
        int k = i >> 6, n = i & 63;
        W1s[k * 72 + n] = (k < K1) ? W1[k * 64 + n] : 0.f;
    }
    for (int i = tid; i < 64 * 64; i += 128) {
        int k = i >> 6, n = i & 63;
        W2s[k * 72 + n] = W2[i];
    }
    if (tid < 64) { b1s[tid] = b1[tid]; b2s[tid] = b2[tid]; }

    // ---- stage edge features: thread t = tile row t ----
    {
        int e = blockIdx.x * TILE + tid;
        float* row = ef + tid * 44;
        if (e < E) {
            int2 em = g_sorted[e];
            int p = em.x, m = em.y;
            smm[tid] = m;
            float4 pb = bxyz4[p];
            float4 nb = newb4[m];
            const float4* fp = feat4 + (size_t)p * 8;
            #pragma unroll
            for (int q = 0; q < 8; q++)
                ((float4*)row)[q] = fp[q];
            row[32] = pb.y - nb.y;
            row[33] = pb.z - nb.z;
            row[34] = pb.w - nb.w;
            row[35] = 0.f; row[36] = 0.f; row[37] = 0.f; row[38] = 0.f; row[39] = 0.f;
        } else {
            smm[tid] = -1;
            #pragma unroll
            for (int q = 0; q < 10; q++)
                ((float4*)row)[q] = make_float4(0.f, 0.f, 0.f, 0.f);
        }
    }
    __syncthreads();

    // ---- per-warp: 2 m-tiles of 16 rows; layer1 then layer2 fused per m-tile ----
    #pragma unroll
    for (int mt = 0; mt < 2; mt++) {
        int r0 = warp * 32 + mt * 16;
        int ra = r0 + g;               // A-frag row for a0/a2 (a1/a3 use ra+8)

        // ===== Layer 1: C1 = relu(ef @ W1 + b1) =====
        unsigned ahi[5][4], alo[5][4];
        #pragma unroll
        for (int kf = 0; kf < 5; kf++) {
            int c0 = kf * 8 + tg;
            float f0 = ef[ra * 44 + c0];
            float f1 = ef[(ra + 8) * 44 + c0];
            float f2 = ef[ra * 44 + c0 + 4];
            float f3 = ef[(ra + 8) * 44 + c0 + 4];
            ahi[kf][0] = tf32_hi(f0); alo[kf][0] = __float_as_uint(f0 - __uint_as_float(ahi[kf][0]));
            ahi[kf][1] = tf32_hi(f1); alo[kf][1] = __float_as_uint(f1 - __uint_as_float(ahi[kf][1]));
            ahi[kf][2] = tf32_hi(f2); alo[kf][2] = __float_as_uint(f2 - __uint_as_float(ahi[kf][2]));
            ahi[kf][3] = tf32_hi(f3); alo[kf][3] = __float_as_uint(f3 - __uint_as_float(ahi[kf][3]));
        }
        #pragma unroll
        for (int nt = 0; nt < 8; nt++) {
            float c0 = 0.f, c1 = 0.f, c2 = 0.f, c3 = 0.f;
            #pragma unroll
            for (int kf = 0; kf < 5; kf++) {
                int kb = kf * 8 + tg;
                int nb = nt * 8 + g;
                float w0 = W1s[kb * 72 + nb];
                float w1 = W1s[(kb + 4) * 72 + nb];
                unsigned bh0 = tf32_hi(w0), bh1 = tf32_hi(w1);
                unsigned bl0 = __float_as_uint(w0 - __uint_as_float(bh0));
                unsigned bl1 = __float_as_uint(w1 - __uint_as_float(bh1));
                mma_tf32(c0, c1, c2, c3, ahi[kf][0], ahi[kf][1], ahi[kf][2], ahi[kf][3], bh0, bh1);
                mma_tf32(c0, c1, c2, c3, alo[kf][0], alo[kf][1], alo[kf][2], alo[kf][3], bh0, bh1);
                mma_tf32(c0, c1, c2, c3, ahi[kf][0], ahi[kf][1], ahi[kf][2], ahi[kf][3], bl0, bl1);
            }
            int col = nt * 8 + 2 * tg;
            float2 v0 = make_float2(fmaxf(c0 + b1s[col], 0.f), fmaxf(c1 + b1s[col + 1], 0.f));
            float2 v1 = make_float2(fmaxf(c2 + b1s[col], 0.f), fmaxf(c3 + b1s[col + 1], 0.f));
            *(float2*)&C1[ra * 68 + col]       = v0;
            *(float2*)&C1[(ra + 8) * 68 + col] = v1;
        }
        __syncwarp();

        // ===== Layer 2: O = relu(C1 @ W2 + b2), written over C1 =====
        unsigned ahi2[8][4], alo2[8][4];
        #pragma unroll
        for (int kf = 0; kf < 8; kf++) {
            int c0 = kf * 8 + tg;
            float f0 = C1[ra * 68 + c0];
            float f1 = C1[(ra + 8) * 68 + c0];
            float f2 = C1[ra * 68 + c0 + 4];
            float f3 = C1[(ra + 8) * 68 + c0 + 4];
            ahi2[kf][0] = tf32_hi(f0); alo2[kf][0] = __float_as_uint(f0 - __uint_as_float(ahi2[kf][0]));
            ahi2[kf][1] = tf32_hi(f1); alo2[kf][1] = __float_as_uint(f1 - __uint_as_float(ahi2[kf][1]));
            ahi2[kf][2] = tf32_hi(f2); alo2[kf][2] = __float_as_uint(f2 - __uint_as_float(ahi2[kf][2]));
            ahi2[kf][3] = tf32_hi(f3); alo2[kf][3] = __float_as_uint(f3 - __uint_as_float(ahi2[kf][3]));
        }
        __syncwarp();   // all lanes done reading C1 rows before overwrite
        #pragma unroll
        for (int nt = 0; nt < 8; nt++) {
            float c0 = 0.f, c1 = 0.f, c2 = 0.f, c3 = 0.f;
            #pragma unroll
            for (int kf = 0; kf < 8; kf++) {
                int kb = kf * 8 + tg;
                int nb = nt * 8 + g;
                float w0 = W2s[kb * 72 + nb];
                float w1 = W2s[(kb + 4) * 72 + nb];
                unsigned bh0 = tf32_hi(w0), bh1 = tf32_hi(w1);
                unsigned bl0 = __float_as_uint(w0 - __uint_as_float(bh0));
                unsigned bl1 = __float_as_uint(w1 - __uint_as_float(bh1));
                mma_tf32(c0, c1, c2, c3, ahi2[kf][0], ahi2[kf][1], ahi2[kf][2], ahi2[kf][3], bh0, bh1);
                mma_tf32(c0, c1, c2, c3, alo2[kf][0], alo2[kf][1], alo2[kf][2], alo2[kf][3], bh0, bh1);
                mma_tf32(c0, c1, c2, c3, ahi2[kf][0], ahi2[kf][1], ahi2[kf][2], ahi2[kf][3], bl0, bl1);
            }
            int col = nt * 8 + 2 * tg;
            float2 v0 = make_float2(fmaxf(c0 + b2s[col], 0.f), fmaxf(c1 + b2s[col + 1], 0.f));
            float2 v1 = make_float2(fmaxf(c2 + b2s[col], 0.f), fmaxf(c3 + b2s[col + 1], 0.f));
            *(float2*)&C1[ra * 68 + col]       = v0;
            *(float2*)&C1[(ra + 8) * 68 + col] = v1;
        }
        __syncwarp();
    }
    __syncthreads();

    // ---- segment-max reduction over the sorted tile ----
    {
        int c  = tid & 63;
        int rs = (tid >> 6) * 64;
        float best = 0.f;
        int cur = -1;
        #pragma unroll 1
        for (int r = rs; r < rs + 64; r++) {
            int m = smm[r];
            if (m < 0) break;               // only trailing padding rows
            if (m != cur) {
                if (cur >= 0)
                    atomicMax(&outf[(size_t)cur * 64 + c], __float_as_int(best));
                cur = m;
                best = 0.f;
            }
            best = fmaxf(best, C1[r * 68 + c]);
        }
        if (cur >= 0)
            atomicMax(&outf[(size_t)cur * 64 + c], __float_as_int(best));
    }
}

// ---------------------------------------------------------------------------
extern "C" void kernel_launch(void* const* d_in, const int* in_sizes, int n_in,
                              void* d_out, int out_size)
{
    const float* point_bxyz = (const float*)d_in[0];
    const float* point_feat = (const float*)d_in[1];
    const int*   sample_idx = (const int*)  d_in[2];
    const int*   e_point    = (const int*)  d_in[3];
    const int*   e_new      = (const int*)  d_in[4];
    const float* W1         = (const float*)d_in[5];
    const float* b1         = (const float*)d_in[6];
    const float* W2         = (const float*)d_in[7];
    const float* b2         = (const float*)d_in[8];

    float* out = (float*)d_out;
    int M = in_sizes[2];
    int E = in_sizes[3];

    // Unconditional (no static guards allowed). Host-side attribute set; legal
    // during graph capture since it is not a stream operation.
    cudaFuncSetAttribute(k_main_tc, cudaFuncAttributeMaxDynamicSharedMemorySize,
                         S_TOT * (int)sizeof(float));

    k_init<<<1024, 256>>>((const float4*)point_bxyz, sample_idx, out, M);
    k_hist<<<(E + 255) / 256, 256>>>(e_new, E);

    int NB = (M + SCAN_BLK - 1) / SCAN_BLK;
    k_scan1<<<NB, SCAN_BLK>>>(M);
    k_scan2<<<1, 256>>>(NB);
    k_scan3<<<(M + 255) / 256, 256>>>(M);

    k_scatter<<<(E + 255) / 256, 256>>>(e_point, e_new, E);

    int nblk = (E + TILE - 1) / TILE;
    k_main_tc<<<nblk, 128, S_TOT * sizeof(float)>>>(
        (const float4*)point_bxyz, (const float4*)point_feat,
        W1, b1, W2, b2,
        (const float4*)out,
        (int*)(out + 4 * (size_t)M),
        E);
}

// round 6
// speedup vs baseline: 1.2573x; 1.2573x over previous
#include <cuda_runtime.h>

// GraphConvDown: per-edge MLP (35 -> 64 -> 64) + scatter-max onto M sampled points.
// Round 6: tensor-core main kernel with pre-split tf32 hi/lo weights (no cvt/sub in
// the inner loops), 64-edge tiles, 8 tiles per block (weights staged once per block),
// and one fewer preprocessing launch so ncu's -s 5 window lands on the main kernel.
//
// Output layout (float32): out[0..4M) = new_bxyz [M,4]; out[4M..4M+64M) = new_feat [M,64]

#define K1 35
#define MAXM 131072
#define MAXE 2000128
#define SCAN_BLK 1024
#define TILE 64
#define TPB 8               // tiles per block

// ---------- static scratch ----------
__device__ int   g_cnt[MAXM];
__device__ int   g_incl[MAXM];
__device__ int   g_cursor[MAXM];
__device__ int   g_bsum[256];
__device__ int   g_btop[256];
__device__ int2  g_sorted[MAXE];      // (e_point, e_new) sorted by e_new
__device__ float g_W1h[40 * 64], g_W1l[40 * 64];   // padded 35->40, tf32 hi/lo
__device__ float g_W2h[64 * 64], g_W2l[64 * 64];

__device__ __forceinline__ unsigned tf32_hi(float f) {
    unsigned r;
    asm("cvt.rna.tf32.f32 %0, %1;" : "=r"(r) : "f"(f));
    return r;
}

// ---------------------------------------------------------------------------
// K_init: gather new_bxyz, zero feat region + counters, split weights hi/lo.
// ---------------------------------------------------------------------------
__global__ void k_init(const float4* __restrict__ bxyz4,
                       const int* __restrict__ sample_idx,
                       const float* __restrict__ W1,
                       const float* __restrict__ W2,
                       float* __restrict__ out, int M) {
    int i = blockIdx.x * blockDim.x + threadIdx.x;
    int stride = gridDim.x * blockDim.x;
    float4* ob = (float4*)out;
    for (int j = i; j < M; j += stride) {
        ob[j] = bxyz4[sample_idx[j]];
        g_cnt[j] = 0;
        g_cursor[j] = 0;
    }
    float4* fz = (float4*)(out + 4 * (size_t)M);
    int tot = M * 16;
    for (int j = i; j < tot; j += stride)
        fz[j] = make_float4(0.f, 0.f, 0.f, 0.f);
    // weight split
    for (int j = i; j < 40 * 64; j += stride) {
        int k = j >> 6, n = j & 63;
        float f = (k < K1) ? W1[k * 64 + n] : 0.f;
        float h = __uint_as_float(tf32_hi(f));
        g_W1h[j] = h;
        g_W1l[j] = f - h;
    }
    for (int j = i; j < 64 * 64; j += stride) {
        float f = W2[j];
        float h = __uint_as_float(tf32_hi(f));
        g_W2h[j] = h;
        g_W2l[j] = f - h;
    }
}

__global__ void k_hist(const int* __restrict__ e_new, int E) {
    int i = blockIdx.x * blockDim.x + threadIdx.x;
    if (i < E) atomicAdd(&g_cnt[e_new[i]], 1);
}

__global__ void k_scan1(int M) {
    __shared__ int sh[SCAN_BLK];
    int i = blockIdx.x * SCAN_BLK + threadIdx.x;
    int v = (i < M) ? g_cnt[i] : 0;
    sh[threadIdx.x] = v;
    __syncthreads();
    for (int d = 1; d < SCAN_BLK; d <<= 1) {
        int t = (threadIdx.x >= d) ? sh[threadIdx.x - d] : 0;
        __syncthreads();
        sh[threadIdx.x] += t;
        __syncthreads();
    }
    if (i < M) g_incl[i] = sh[threadIdx.x];
    if (threadIdx.x == SCAN_BLK - 1) g_bsum[blockIdx.x] = sh[SCAN_BLK - 1];
}
__global__ void k_scan2(int NB) {
    __shared__ int sh[256];
    int v = (threadIdx.x < NB) ? g_bsum[threadIdx.x] : 0;
    sh[threadIdx.x] = v;
    __syncthreads();
    for (int d = 1; d < 256; d <<= 1) {
        int t = (threadIdx.x >= d) ? sh[threadIdx.x - d] : 0;
        __syncthreads();
        sh[threadIdx.x] += t;
        __syncthreads();
    }
    g_btop[threadIdx.x] = sh[threadIdx.x] - v;
}

// scatter: base computed inline (replaces old k_scan3); g_cursor pre-zeroed in k_init
__global__ void k_scatter(const int* __restrict__ e_point,
                          const int* __restrict__ e_new, int E) {
    int i = blockIdx.x * blockDim.x + threadIdx.x;
    if (i < E) {
        int m = e_new[i];
        int base = g_incl[m] - g_cnt[m] + g_btop[m >> 10];
        int pos = base + atomicAdd(&g_cursor[m], 1);
        g_sorted[pos] = make_int2(e_point[i], m);
    }
}

// ---------------------------------------------------------------------------
__device__ __forceinline__ void mma_tf32(float& c0, float& c1, float& c2, float& c3,
                                         unsigned a0, unsigned a1, unsigned a2, unsigned a3,
                                         unsigned b0, unsigned b1) {
    asm volatile("mma.sync.aligned.m16n8k8.row.col.f32.tf32.tf32.f32 "
                 "{%0,%1,%2,%3}, {%4,%5,%6,%7}, {%8,%9}, {%0,%1,%2,%3};"
                 : "+f"(c0), "+f"(c1), "+f"(c2), "+f"(c3)
                 : "r"(a0), "r"(a1), "r"(a2), "r"(a3), "r"(b0), "r"(b1));
}

// SMEM layout (float offsets). Stride 72 is conflict-free for the lane patterns.
#define S_W1H  0                       // [40][72]
#define S_W1L  (S_W1H + 40 * 72)       // [40][72]
#define S_W2H  (S_W1L + 40 * 72)       // [64][72]
#define S_W2L  (S_W2H + 64 * 72)       // [64][72]
#define S_B1   (S_W2L + 64 * 72)       // [64]
#define S_B2   (S_B1 + 64)             // [64]
#define S_MM   (S_B2 + 64)             // [64] ints
#define S_EF   (S_MM + 64)             // [64][44]
#define S_C1   (S_EF + 64 * 44)        // [64][68]
#define S_TOT  (S_C1 + 64 * 68)        // 22336 floats = 89344 B

// ---------------------------------------------------------------------------
// Main kernel: 128 threads (4 warps). Each block stages weights once, then
// processes TPB tiles of 64 sorted edges; warp w owns rows [w*16, w*16+16).
// ---------------------------------------------------------------------------
__global__ __launch_bounds__(128)
void k_main_tc(const float4* __restrict__ bxyz4,
               const float4* __restrict__ feat4,
               const float*  __restrict__ b1, const float* __restrict__ b2,
               const float4* __restrict__ newb4,
               int*          __restrict__ outf,
               int E)
{
    extern __shared__ float sm[];
    float* W1h = sm + S_W1H;
    float* W1l = sm + S_W1L;
    float* W2h = sm + S_W2H;
    float* W2l = sm + S_W2L;
    float* b1s = sm + S_B1;
    float* b2s = sm + S_B2;
    int*   smm = (int*)(sm + S_MM);
    float* ef  = sm + S_EF;
    float* C1  = sm + S_C1;

    int tid  = threadIdx.x;
    int warp = tid >> 5;
    int lane = tid & 31;
    int g    = lane >> 2;
    int tg   = lane & 3;

    // ---- stage weights (once per block) ----
    for (int i = tid; i < 40 * 64; i += 128) {
        int k = i >> 6, n = i & 63;
        W1h[k * 72 + n] = g_W1h[i];
        W1l[k * 72 + n] = g_W1l[i];
    }
    for (int i = tid; i < 64 * 64; i += 128) {
        int k = i >> 6, n = i & 63;
        W2h[k * 72 + n] = g_W2h[i];
        W2l[k * 72 + n] = g_W2l[i];
    }
    if (tid < 64) { b1s[tid] = b1[tid]; b2s[tid] = b2[tid]; }

    // ---- tile loop ----
    for (int tb = 0; tb < TPB; tb++) {
        int base = (blockIdx.x * TPB + tb) * TILE;
        if (base >= E) break;
        __syncthreads();   // protects ef/C1/smm reuse (also covers weight staging on tb=0)

        // stage 64 edge rows, 2 threads per row
        {
            int row  = tid >> 1;
            int half = tid & 1;
            int e = base + row;
            float* rp = ef + row * 44;
            if (e < E) {
                int2 em = g_sorted[e];
                int p = em.x, m = em.y;
                const float4* fp = feat4 + (size_t)p * 8;
                if (half == 0) {
                    smm[row] = m;
                    #pragma unroll
                    for (int q = 0; q < 4; q++) ((float4*)rp)[q] = fp[q];
                } else {
                    #pragma unroll
                    for (int q = 4; q < 8; q++) ((float4*)rp)[q] = fp[q];
                    float4 pb = bxyz4[p];
                    float4 nb = newb4[m];
                    rp[32] = pb.y - nb.y;
                    rp[33] = pb.z - nb.z;
                    rp[34] = pb.w - nb.w;
                    rp[35] = 0.f; rp[36] = 0.f; rp[37] = 0.f; rp[38] = 0.f; rp[39] = 0.f;
                }
            } else {
                if (half == 0) {
                    smm[row] = -1;
                    #pragma unroll
                    for (int q = 0; q < 4; q++) ((float4*)rp)[q] = make_float4(0.f,0.f,0.f,0.f);
                } else {
                    #pragma unroll
                    for (int q = 4; q < 10; q++) ((float4*)rp)[q] = make_float4(0.f,0.f,0.f,0.f);
                }
            }
        }
        __syncthreads();

        int ra = warp * 16 + g;

        // ===== Layer 1: C1 = relu(ef @ W1 + b1) =====
        {
            unsigned ahi[5][4], alo[5][4];
            #pragma unroll
            for (int kf = 0; kf < 5; kf++) {
                int c0 = kf * 8 + tg;
                float f0 = ef[ra * 44 + c0];
                float f1 = ef[(ra + 8) * 44 + c0];
                float f2 = ef[ra * 44 + c0 + 4];
                float f3 = ef[(ra + 8) * 44 + c0 + 4];
                ahi[kf][0] = tf32_hi(f0); alo[kf][0] = __float_as_uint(f0 - __uint_as_float(ahi[kf][0]));
                ahi[kf][1] = tf32_hi(f1); alo[kf][1] = __float_as_uint(f1 - __uint_as_float(ahi[kf][1]));
                ahi[kf][2] = tf32_hi(f2); alo[kf][2] = __float_as_uint(f2 - __uint_as_float(ahi[kf][2]));
                ahi[kf][3] = tf32_hi(f3); alo[kf][3] = __float_as_uint(f3 - __uint_as_float(ahi[kf][3]));
            }
            #pragma unroll
            for (int nt = 0; nt < 8; nt++) {
                float c0 = 0.f, c1 = 0.f, c2 = 0.f, c3 = 0.f;
                #pragma unroll
                for (int kf = 0; kf < 5; kf++) {
                    int kb = kf * 8 + tg;
                    int nb = nt * 8 + g;
                    unsigned bh0 = __float_as_uint(W1h[kb * 72 + nb]);
                    unsigned bh1 = __float_as_uint(W1h[(kb + 4) * 72 + nb]);
                    unsigned bl0 = __float_as_uint(W1l[kb * 72 + nb]);
                    unsigned bl1 = __float_as_uint(W1l[(kb + 4) * 72 + nb]);
                    mma_tf32(c0, c1, c2, c3, ahi[kf][0], ahi[kf][1], ahi[kf][2], ahi[kf][3], bh0, bh1);
                    mma_tf32(c0, c1, c2, c3, alo[kf][0], alo[kf][1], alo[kf][2], alo[kf][3], bh0, bh1);
                    mma_tf32(c0, c1, c2, c3, ahi[kf][0], ahi[kf][1], ahi[kf][2], ahi[kf][3], bl0, bl1);
                }
                int col = nt * 8 + 2 * tg;
                float2 v0 = make_float2(fmaxf(c0 + b1s[col], 0.f), fmaxf(c1 + b1s[col + 1], 0.f));
                float2 v1 = make_float2(fmaxf(c2 + b1s[col], 0.f), fmaxf(c3 + b1s[col + 1], 0.f));
                *(float2*)&C1[ra * 68 + col]       = v0;
                *(float2*)&C1[(ra + 8) * 68 + col] = v1;
            }
        }
        __syncwarp();

        // ===== Layer 2: O = relu(C1 @ W2 + b2), written over C1 =====
        {
            unsigned ahi[8][4], alo[8][4];
            #pragma unroll
            for (int kf = 0; kf < 8; kf++) {
                int c0 = kf * 8 + tg;
                float f0 = C1[ra * 68 + c0];
                float f1 = C1[(ra + 8) * 68 + c0];
                float f2 = C1[ra * 68 + c0 + 4];
                float f3 = C1[(ra + 8) * 68 + c0 + 4];
                ahi[kf][0] = tf32_hi(f0); alo[kf][0] = __float_as_uint(f0 - __uint_as_float(ahi[kf][0]));
                ahi[kf][1] = tf32_hi(f1); alo[kf][1] = __float_as_uint(f1 - __uint_as_float(ahi[kf][1]));
                ahi[kf][2] = tf32_hi(f2); alo[kf][2] = __float_as_uint(f2 - __uint_as_float(ahi[kf][2]));
                ahi[kf][3] = tf32_hi(f3); alo[kf][3] = __float_as_uint(f3 - __uint_as_float(ahi[kf][3]));
            }
            __syncwarp();   // done reading C1 rows before overwrite
            #pragma unroll
            for (int nt = 0; nt < 8; nt++) {
                float c0 = 0.f, c1 = 0.f, c2 = 0.f, c3 = 0.f;
                #pragma unroll
                for (int kf = 0; kf < 8; kf++) {
                    int kb = kf * 8 + tg;
                    int nb = nt * 8 + g;
                    unsigned bh0 = __float_as_uint(W2h[kb * 72 + nb]);
                    unsigned bh1 = __float_as_uint(W2h[(kb + 4) * 72 + nb]);
                    unsigned bl0 = __float_as_uint(W2l[kb * 72 + nb]);
                    unsigned bl1 = __float_as_uint(W2l[(kb + 4) * 72 + nb]);
                    mma_tf32(c0, c1, c2, c3, ahi[kf][0], ahi[kf][1], ahi[kf][2], ahi[kf][3], bh0, bh1);
                    mma_tf32(c0, c1, c2, c3, alo[kf][0], alo[kf][1], alo[kf][2], alo[kf][3], bh0, bh1);
                    mma_tf32(c0, c1, c2, c3, ahi[kf][0], ahi[kf][1], ahi[kf][2], ahi[kf][3], bl0, bl1);
                }
                int col = nt * 8 + 2 * tg;
                float2 v0 = make_float2(fmaxf(c0 + b2s[col], 0.f), fmaxf(c1 + b2s[col + 1], 0.f));
                float2 v1 = make_float2(fmaxf(c2 + b2s[col], 0.f), fmaxf(c3 + b2s[col + 1], 0.f));
                *(float2*)&C1[ra * 68 + col]       = v0;
                *(float2*)&C1[(ra + 8) * 68 + col] = v1;
            }
        }
        __syncthreads();

        // ---- segment-max over the sorted 64-row tile ----
        {
            int c  = tid & 63;
            int rs = (tid >> 6) * 32;
            float best = 0.f;
            int cur = -1;
            #pragma unroll 1
            for (int r = rs; r < rs + 32; r++) {
                int m = smm[r];
                if (m < 0) break;           // trailing padding only
                if (m != cur) {
                    if (cur >= 0)
                        atomicMax(&outf[(size_t)cur * 64 + c], __float_as_int(best));
                    cur = m;
                    best = 0.f;
                }
                best = fmaxf(best, C1[r * 68 + c]);
            }
            if (cur >= 0)
                atomicMax(&outf[(size_t)cur * 64 + c], __float_as_int(best));
        }
    }
}

// ---------------------------------------------------------------------------
extern "C" void kernel_launch(void* const* d_in, const int* in_sizes, int n_in,
                              void* d_out, int out_size)
{
    const float* point_bxyz = (const float*)d_in[0];
    const float* point_feat = (const float*)d_in[1];
    const int*   sample_idx = (const int*)  d_in[2];
    const int*   e_point    = (const int*)  d_in[3];
    const int*   e_new      = (const int*)  d_in[4];
    const float* W1         = (const float*)d_in[5];
    const float* b1         = (const float*)d_in[6];
    const float* W2         = (const float*)d_in[7];
    const float* b2         = (const float*)d_in[8];

    float* out = (float*)d_out;
    int M = in_sizes[2];
    int E = in_sizes[3];

    cudaFuncSetAttribute(k_main_tc, cudaFuncAttributeMaxDynamicSharedMemorySize,
                         S_TOT * (int)sizeof(float));

    k_init<<<1024, 256>>>((const float4*)point_bxyz, sample_idx, W1, W2, out, M);
    k_hist<<<(E + 255) / 256, 256>>>(e_new, E);

    int NB = (M + SCAN_BLK - 1) / SCAN_BLK;
    k_scan1<<<NB, SCAN_BLK>>>(M);
    k_scan2<<<1, 256>>>(NB);

    k_scatter<<<(E + 255) / 256, 256>>>(e_point, e_new, E);

    int nblk = (E + TILE * TPB - 1) / (TILE * TPB);
    k_main_tc<<<nblk, 128, S_TOT * sizeof(float)>>>(
        (const float4*)point_bxyz, (const float4*)point_feat,
        b1, b2,
        (const float4*)out,
        (int*)(out + 4 * (size_t)M),
        E);
}

// round 7
// speedup vs baseline: 1.9743x; 1.5703x over previous
#include <cuda_runtime.h>

// GraphConvDown: per-edge MLP (35 -> 64 -> 64) + scatter-max onto M sampled points.
// Round 7: bf16 m16n8k16 tensor cores with 3-term error-compensated split
// (AhiBhi + AloBhi + AhiBlo), pre-split packed-bf16 weights, bf16-packed C1,
// 68.9 KB smem (3 blocks/SM). mma count per warp-tile drops 312 -> 168 and
// LDS ~470 -> ~280 vs the round-6 tf32 scheme.
//
// Output layout (float32): out[0..4M) = new_bxyz [M,4]; out[4M..4M+64M) = new_feat [M,64]

#define K1 35
#define MAXM 131072
#define MAXE 2000128
#define SCAN_BLK 1024
#define TILE 64
#define TPB 8

// ---------- static scratch ----------
__device__ int      g_cnt[MAXM];
__device__ int      g_incl[MAXM];
__device__ int      g_cursor[MAXM];
__device__ int      g_bsum[256];
__device__ int      g_btop[256];
__device__ int2     g_sorted[MAXE];
__device__ unsigned g_W1hi[24 * 64], g_W1lo[24 * 64];   // k padded 35->48, packed (k,k+1) bf16
__device__ unsigned g_W2hi[32 * 64], g_W2lo[32 * 64];   // k=64

// pack two floats to bf16x2: low half = x (lower k), high half = y (k+1)
__device__ __forceinline__ unsigned pack_bf16(float x, float y) {
    unsigned r;
    asm("cvt.rn.bf16x2.f32 %0, %1, %2;" : "=r"(r) : "f"(y), "f"(x));
    return r;
}
__device__ __forceinline__ void split_pair(float x, float y, unsigned& hi, unsigned& lo) {
    hi = pack_bf16(x, y);
    float hx = __uint_as_float(hi << 16);
    float hy = __uint_as_float(hi & 0xffff0000u);
    lo = pack_bf16(x - hx, y - hy);
}

// ---------------------------------------------------------------------------
// K_init: gather new_bxyz, zero feat region + counters, split-pack weights.
// ---------------------------------------------------------------------------
__global__ void k_init(const float4* __restrict__ bxyz4,
                       const int* __restrict__ sample_idx,
                       const float* __restrict__ W1,
                       const float* __restrict__ W2,
                       float* __restrict__ out, int M) {
    int i = blockIdx.x * blockDim.x + threadIdx.x;
    int stride = gridDim.x * blockDim.x;
    float4* ob = (float4*)out;
    for (int j = i; j < M; j += stride) {
        ob[j] = bxyz4[sample_idx[j]];
        g_cnt[j] = 0;
        g_cursor[j] = 0;
    }
    float4* fz = (float4*)(out + 4 * (size_t)M);
    int tot = M * 16;
    for (int j = i; j < tot; j += stride)
        fz[j] = make_float4(0.f, 0.f, 0.f, 0.f);
    for (int j = i; j < 24 * 64; j += stride) {
        int kp = j >> 6, n = j & 63;
        int k0 = 2 * kp, k1 = 2 * kp + 1;
        float w0 = (k0 < K1) ? W1[k0 * 64 + n] : 0.f;
        float w1 = (k1 < K1) ? W1[k1 * 64 + n] : 0.f;
        unsigned hi, lo;
        split_pair(w0, w1, hi, lo);
        g_W1hi[j] = hi;
        g_W1lo[j] = lo;
    }
    for (int j = i; j < 32 * 64; j += stride) {
        int kp = j >> 6, n = j & 63;
        float w0 = W2[(2 * kp) * 64 + n];
        float w1 = W2[(2 * kp + 1) * 64 + n];
        unsigned hi, lo;
        split_pair(w0, w1, hi, lo);
        g_W2hi[j] = hi;
        g_W2lo[j] = lo;
    }
}

__global__ void k_hist(const int* __restrict__ e_new, int E) {
    int i = blockIdx.x * blockDim.x + threadIdx.x;
    if (i < E) atomicAdd(&g_cnt[e_new[i]], 1);
}

__global__ void k_scan1(int M) {
    __shared__ int sh[SCAN_BLK];
    int i = blockIdx.x * SCAN_BLK + threadIdx.x;
    int v = (i < M) ? g_cnt[i] : 0;
    sh[threadIdx.x] = v;
    __syncthreads();
    for (int d = 1; d < SCAN_BLK; d <<= 1) {
        int t = (threadIdx.x >= d) ? sh[threadIdx.x - d] : 0;
        __syncthreads();
        sh[threadIdx.x] += t;
        __syncthreads();
    }
    if (i < M) g_incl[i] = sh[threadIdx.x];
    if (threadIdx.x == SCAN_BLK - 1) g_bsum[blockIdx.x] = sh[SCAN_BLK - 1];
}
__global__ void k_scan2(int NB) {
    __shared__ int sh[256];
    int v = (threadIdx.x < NB) ? g_bsum[threadIdx.x] : 0;
    sh[threadIdx.x] = v;
    __syncthreads();
    for (int d = 1; d < 256; d <<= 1) {
        int t = (threadIdx.x >= d) ? sh[threadIdx.x - d] : 0;
        __syncthreads();
        sh[threadIdx.x] += t;
        __syncthreads();
    }
    g_btop[threadIdx.x] = sh[threadIdx.x] - v;
}

__global__ void k_scatter(const int* __restrict__ e_point,
                          const int* __restrict__ e_new, int E) {
    int i = blockIdx.x * blockDim.x + threadIdx.x;
    if (i < E) {
        int m = e_new[i];
        int base = g_incl[m] - g_cnt[m] + g_btop[m >> 10];
        int pos = base + atomicAdd(&g_cursor[m], 1);
        g_sorted[pos] = make_int2(e_point[i], m);
    }
}

// ---------------------------------------------------------------------------
__device__ __forceinline__ void mma_bf16(float& c0, float& c1, float& c2, float& c3,
                                         unsigned a0, unsigned a1, unsigned a2, unsigned a3,
                                         unsigned b0, unsigned b1) {
    asm volatile("mma.sync.aligned.m16n8k16.row.col.f32.bf16.bf16.f32 "
                 "{%0,%1,%2,%3}, {%4,%5,%6,%7}, {%8,%9}, {%0,%1,%2,%3};"
                 : "+f"(c0), "+f"(c1), "+f"(c2), "+f"(c3)
                 : "r"(a0), "r"(a1), "r"(a2), "r"(a3), "r"(b0), "r"(b1));
}

// SMEM layout (32-bit word offsets).
// Weights stride 72 (u32): bank = 8*kp + n (mod 32) -> conflict-free.
// C1 stride 36: bank = 4*g + tg -> conflict-free. Scratch stride 68 fp32.
#define S_W1H  0                        // [24][72] u32
#define S_W1L  (S_W1H + 24 * 72)
#define S_W2H  (S_W1L + 24 * 72)        // [32][72]
#define S_W2L  (S_W2H + 32 * 72)
#define S_B1   (S_W2L + 32 * 72)        // [64] f32
#define S_B2   (S_B1 + 64)
#define S_MM   (S_B2 + 64)              // [64] int
#define S_SC   (S_MM + 64)              // [64][68] f32 (ef K=48 padded / layer2 out)
#define S_C1H  (S_SC + 64 * 68)         // [64][36] u32
#define S_C1L  (S_C1H + 64 * 36)
#define S_TOT  (S_C1L + 64 * 36)        // 17216 words = 68864 B

// ---------------------------------------------------------------------------
// Main kernel: 128 threads (4 warps); warp w owns rows [16w, 16w+16) of each
// 64-edge tile; TPB tiles per block; weights staged once per block.
// ---------------------------------------------------------------------------
__global__ __launch_bounds__(128)
void k_main_tc(const float4* __restrict__ bxyz4,
               const float4* __restrict__ feat4,
               const float*  __restrict__ b1, const float* __restrict__ b2,
               const float4* __restrict__ newb4,
               int*          __restrict__ outf,
               int E)
{
    extern __shared__ float sm[];
    unsigned* W1h = (unsigned*)(sm + S_W1H);
    unsigned* W1l = (unsigned*)(sm + S_W1L);
    unsigned* W2h = (unsigned*)(sm + S_W2H);
    unsigned* W2l = (unsigned*)(sm + S_W2L);
    float*    b1s = sm + S_B1;
    float*    b2s = sm + S_B2;
    int*      smm = (int*)(sm + S_MM);
    float*    sc  = sm + S_SC;
    unsigned* C1h = (unsigned*)(sm + S_C1H);
    unsigned* C1l = (unsigned*)(sm + S_C1L);

    int tid  = threadIdx.x;
    int warp = tid >> 5;
    int lane = tid & 31;
    int g    = lane >> 2;
    int tg   = lane & 3;

    // ---- stage packed weights (once per block) ----
    for (int i = tid; i < 24 * 64; i += 128) {
        int kp = i >> 6, n = i & 63;
        W1h[kp * 72 + n] = g_W1hi[i];
        W1l[kp * 72 + n] = g_W1lo[i];
    }
    for (int i = tid; i < 32 * 64; i += 128) {
        int kp = i >> 6, n = i & 63;
        W2h[kp * 72 + n] = g_W2hi[i];
        W2l[kp * 72 + n] = g_W2lo[i];
    }
    if (tid < 64) { b1s[tid] = b1[tid]; b2s[tid] = b2[tid]; }

    for (int tb = 0; tb < TPB; tb++) {
        int base = (blockIdx.x * TPB + tb) * TILE;
        if (base >= E) break;
        __syncthreads();    // prior epilogue done before buffers are reused

        // ---- stage 64 edge rows into scratch, K padded to 48 (warp-local rows) ----
        {
            int row  = tid >> 1;
            int half = tid & 1;
            int e = base + row;
            float* rp = sc + row * 68;
            if (e < E) {
                int2 em = g_sorted[e];
                int p = em.x, m = em.y;
                const float4* fp = feat4 + (size_t)p * 8;
                if (half == 0) {
                    smm[row] = m;
                    #pragma unroll
                    for (int q = 0; q < 4; q++) ((float4*)rp)[q] = fp[q];
                } else {
                    #pragma unroll
                    for (int q = 4; q < 8; q++) ((float4*)rp)[q] = fp[q];
                    float4 pb = bxyz4[p];
                    float4 nb = newb4[m];
                    ((float4*)rp)[8]  = make_float4(pb.y - nb.y, pb.z - nb.z, pb.w - nb.w, 0.f);
                    ((float4*)rp)[9]  = make_float4(0.f, 0.f, 0.f, 0.f);
                    ((float4*)rp)[10] = make_float4(0.f, 0.f, 0.f, 0.f);
                    ((float4*)rp)[11] = make_float4(0.f, 0.f, 0.f, 0.f);
                }
            } else {
                if (half == 0) {
                    smm[row] = -1;
                    #pragma unroll
                    for (int q = 0; q < 4; q++) ((float4*)rp)[q] = make_float4(0.f,0.f,0.f,0.f);
                } else {
                    #pragma unroll
                    for (int q = 4; q < 12; q++) ((float4*)rp)[q] = make_float4(0.f,0.f,0.f,0.f);
                }
            }
        }
        __syncwarp();       // staging is warp-local; compute rows are warp-local too

        int ra = warp * 16 + g;

        // ===== Layer 1: C1 = relu(ef @ W1 + b1), K=48 (3 kf) =====
        {
            unsigned ahi[3][4], alo[3][4];
            #pragma unroll
            for (int kf = 0; kf < 3; kf++) {
                int k0 = kf * 16 + 2 * tg;
                float2 p0 = *(float2*)&sc[ra * 68 + k0];
                float2 p1 = *(float2*)&sc[(ra + 8) * 68 + k0];
                float2 p2 = *(float2*)&sc[ra * 68 + k0 + 8];
                float2 p3 = *(float2*)&sc[(ra + 8) * 68 + k0 + 8];
                split_pair(p0.x, p0.y, ahi[kf][0], alo[kf][0]);
                split_pair(p1.x, p1.y, ahi[kf][1], alo[kf][1]);
                split_pair(p2.x, p2.y, ahi[kf][2], alo[kf][2]);
                split_pair(p3.x, p3.y, ahi[kf][3], alo[kf][3]);
            }
            #pragma unroll
            for (int nt = 0; nt < 8; nt++) {
                float c0 = 0.f, c1 = 0.f, c2 = 0.f, c3 = 0.f;
                int nb = nt * 8 + g;
                #pragma unroll
                for (int kf = 0; kf < 3; kf++) {
                    unsigned bh0 = W1h[(kf * 8 + tg) * 72 + nb];
                    unsigned bh1 = W1h[(kf * 8 + tg + 4) * 72 + nb];
                    unsigned bl0 = W1l[(kf * 8 + tg) * 72 + nb];
                    unsigned bl1 = W1l[(kf * 8 + tg + 4) * 72 + nb];
                    mma_bf16(c0, c1, c2, c3, ahi[kf][0], ahi[kf][1], ahi[kf][2], ahi[kf][3], bh0, bh1);
                    mma_bf16(c0, c1, c2, c3, alo[kf][0], alo[kf][1], alo[kf][2], alo[kf][3], bh0, bh1);
                    mma_bf16(c0, c1, c2, c3, ahi[kf][0], ahi[kf][1], ahi[kf][2], ahi[kf][3], bl0, bl1);
                }
                int col = nt * 8 + 2 * tg;
                float v0 = fmaxf(c0 + b1s[col], 0.f);
                float v1 = fmaxf(c1 + b1s[col + 1], 0.f);
                float v2 = fmaxf(c2 + b1s[col], 0.f);
                float v3 = fmaxf(c3 + b1s[col + 1], 0.f);
                unsigned hi, lo;
                int kp = nt * 4 + tg;
                split_pair(v0, v1, hi, lo);
                C1h[ra * 36 + kp] = hi;  C1l[ra * 36 + kp] = lo;
                split_pair(v2, v3, hi, lo);
                C1h[(ra + 8) * 36 + kp] = hi;  C1l[(ra + 8) * 36 + kp] = lo;
            }
        }
        __syncwarp();

        // ===== Layer 2: out = relu(C1 @ W2 + b2), K=64 (4 kf); out -> scratch =====
        {
            unsigned ahi[4][4], alo[4][4];
            #pragma unroll
            for (int kf = 0; kf < 4; kf++) {
                ahi[kf][0] = C1h[ra * 36 + kf * 8 + tg];
                ahi[kf][1] = C1h[(ra + 8) * 36 + kf * 8 + tg];
                ahi[kf][2] = C1h[ra * 36 + kf * 8 + tg + 4];
                ahi[kf][3] = C1h[(ra + 8) * 36 + kf * 8 + tg + 4];
                alo[kf][0] = C1l[ra * 36 + kf * 8 + tg];
                alo[kf][1] = C1l[(ra + 8) * 36 + kf * 8 + tg];
                alo[kf][2] = C1l[ra * 36 + kf * 8 + tg + 4];
                alo[kf][3] = C1l[(ra + 8) * 36 + kf * 8 + tg + 4];
            }
            __syncwarp();   // scratch rows (ef) fully consumed in layer 1; safe to overwrite
            #pragma unroll
            for (int nt = 0; nt < 8; nt++) {
                float c0 = 0.f, c1 = 0.f, c2 = 0.f, c3 = 0.f;
                int nb = nt * 8 + g;
                #pragma unroll
                for (int kf = 0; kf < 4; kf++) {
                    unsigned bh0 = W2h[(kf * 8 + tg) * 72 + nb];
                    unsigned bh1 = W2h[(kf * 8 + tg + 4) * 72 + nb];
                    unsigned bl0 = W2l[(kf * 8 + tg) * 72 + nb];
                    unsigned bl1 = W2l[(kf * 8 + tg + 4) * 72 + nb];
                    mma_bf16(c0, c1, c2, c3, ahi[kf][0], ahi[kf][1], ahi[kf][2], ahi[kf][3], bh0, bh1);
                    mma_bf16(c0, c1, c2, c3, alo[kf][0], alo[kf][1], alo[kf][2], alo[kf][3], bh0, bh1);
                    mma_bf16(c0, c1, c2, c3, ahi[kf][0], ahi[kf][1], ahi[kf][2], ahi[kf][3], bl0, bl1);
                }
                int col = nt * 8 + 2 * tg;
                *(float2*)&sc[ra * 68 + col] =
                    make_float2(fmaxf(c0 + b2s[col], 0.f), fmaxf(c1 + b2s[col + 1], 0.f));
                *(float2*)&sc[(ra + 8) * 68 + col] =
                    make_float2(fmaxf(c2 + b2s[col], 0.f), fmaxf(c3 + b2s[col + 1], 0.f));
            }
        }
        __syncthreads();

        // ---- segment-max over the sorted 64-row tile ----
        {
            int c  = tid & 63;
            int rs = (tid >> 6) * 32;
            float best = 0.f;
            int cur = -1;
            #pragma unroll 1
            for (int r = rs; r < rs + 32; r++) {
                int m = smm[r];
                if (m < 0) break;           // trailing padding only
                if (m != cur) {
                    if (cur >= 0)
                        atomicMax(&outf[(size_t)cur * 64 + c], __float_as_int(best));
                    cur = m;
                    best = 0.f;
                }
                best = fmaxf(best, sc[r * 68 + c]);
            }
            if (cur >= 0)
                atomicMax(&outf[(size_t)cur * 64 + c], __float_as_int(best));
        }
    }
}

// ---------------------------------------------------------------------------
extern "C" void kernel_launch(void* const* d_in, const int* in_sizes, int n_in,
                              void* d_out, int out_size)
{
    const float* point_bxyz = (const float*)d_in[0];
    const float* point_feat = (const float*)d_in[1];
    const int*   sample_idx = (const int*)  d_in[2];
    const int*   e_point    = (const int*)  d_in[3];
    const int*   e_new      = (const int*)  d_in[4];
    const float* W1         = (const float*)d_in[5];
    const float* b1         = (const float*)d_in[6];
    const float* W2         = (const float*)d_in[7];
    const float* b2         = (const float*)d_in[8];

    float* out = (float*)d_out;
    int M = in_sizes[2];
    int E = in_sizes[3];

    cudaFuncSetAttribute(k_main_tc, cudaFuncAttributeMaxDynamicSharedMemorySize,
                         S_TOT * (int)sizeof(float));

    k_init<<<1024, 256>>>((const float4*)point_bxyz, sample_idx, W1, W2, out, M);
    k_hist<<<(E + 255) / 256, 256>>>(e_new, E);

    int NB = (M + SCAN_BLK - 1) / SCAN_BLK;
    k_scan1<<<NB, SCAN_BLK>>>(M);
    k_scan2<<<1, 256>>>(NB);

    k_scatter<<<(E + 255) / 256, 256>>>(e_point, e_new, E);

    int nblk = (E + TILE * TPB - 1) / (TILE * TPB);
    k_main_tc<<<nblk, 128, S_TOT * sizeof(float)>>>(
        (const float4*)point_bxyz, (const float4*)point_feat,
        b1, b2,
        (const float4*)out,
        (int*)(out + 4 * (size_t)M),
        E);
}

// round 9
// speedup vs baseline: 2.3442x; 1.1874x over previous
#include <cuda_runtime.h>

// GraphConvDown: per-edge MLP (35 -> 64 -> 64) + scatter-max onto M sampled points.
// Round 9: legacy mma.sync bf16 (tcgen05 unavailable: harness targets sm_100, not
// sm_100a). vs R7: (a) layer-1 C fragments feed layer-2 A fragments directly in
// registers (C-frag layout == A-frag layout; no C1 smem roundtrip), (b) weight
// hi/lo packed as uint2 so one 64-bit LDS serves both split halves, (c) smem
// 68.9 -> ~49 KB for 4 blocks/SM.
//
// Output layout (float32): out[0..4M) = new_bxyz [M,4]; out[4M..4M+64M) = new_feat [M,64]

#define K1 35
#define MAXM 131072
#define MAXE 2000128
#define SCAN_BLK 1024
#define TILE 64
#define TPB 8

// ---------- static scratch ----------
__device__ int   g_cnt[MAXM];
__device__ int   g_incl[MAXM];
__device__ int   g_cursor[MAXM];
__device__ int   g_bsum[256];
__device__ int   g_btop[256];
__device__ int2  g_sorted[MAXE];
__device__ uint2 g_W1i[24 * 64];   // (hi, lo) bf16x2 pairs, k padded 35->48
__device__ uint2 g_W2i[32 * 64];   // k=64

__device__ __forceinline__ unsigned pack_bf16(float x, float y) {
    unsigned r;
    asm("cvt.rn.bf16x2.f32 %0, %1, %2;" : "=r"(r) : "f"(y), "f"(x));
    return r;
}
__device__ __forceinline__ void split_pair(float x, float y, unsigned& hi, unsigned& lo) {
    hi = pack_bf16(x, y);
    float hx = __uint_as_float(hi << 16);
    float hy = __uint_as_float(hi & 0xffff0000u);
    lo = pack_bf16(x - hx, y - hy);
}

// ---------------------------------------------------------------------------
__global__ void k_init(const float4* __restrict__ bxyz4,
                       const int* __restrict__ sample_idx,
                       const float* __restrict__ W1,
                       const float* __restrict__ W2,
                       float* __restrict__ out, int M) {
    int i = blockIdx.x * blockDim.x + threadIdx.x;
    int stride = gridDim.x * blockDim.x;
    float4* ob = (float4*)out;
    for (int j = i; j < M; j += stride) {
        ob[j] = bxyz4[sample_idx[j]];
        g_cnt[j] = 0;
        g_cursor[j] = 0;
    }
    float4* fz = (float4*)(out + 4 * (size_t)M);
    int tot = M * 16;
    for (int j = i; j < tot; j += stride)
        fz[j] = make_float4(0.f, 0.f, 0.f, 0.f);
    for (int j = i; j < 24 * 64; j += stride) {
        int kp = j >> 6, n = j & 63;
        int k0 = 2 * kp, k1 = 2 * kp + 1;
        float w0 = (k0 < K1) ? W1[k0 * 64 + n] : 0.f;
        float w1 = (k1 < K1) ? W1[k1 * 64 + n] : 0.f;
        unsigned hi, lo;
        split_pair(w0, w1, hi, lo);
        g_W1i[j] = make_uint2(hi, lo);
    }
    for (int j = i; j < 32 * 64; j += stride) {
        int kp = j >> 6, n = j & 63;
        float w0 = W2[(2 * kp) * 64 + n];
        float w1 = W2[(2 * kp + 1) * 64 + n];
        unsigned hi, lo;
        split_pair(w0, w1, hi, lo);
        g_W2i[j] = make_uint2(hi, lo);
    }
}

__global__ void k_hist(const int* __restrict__ e_new, int E) {
    int i = blockIdx.x * blockDim.x + threadIdx.x;
    if (i < E) atomicAdd(&g_cnt[e_new[i]], 1);
}

__global__ void k_scan1(int M) {
    __shared__ int sh[SCAN_BLK];
    int i = blockIdx.x * SCAN_BLK + threadIdx.x;
    int v = (i < M) ? g_cnt[i] : 0;
    sh[threadIdx.x] = v;
    __syncthreads();
    for (int d = 1; d < SCAN_BLK; d <<= 1) {
        int t = (threadIdx.x >= d) ? sh[threadIdx.x - d] : 0;
        __syncthreads();
        sh[threadIdx.x] += t;
        __syncthreads();
    }
    if (i < M) g_incl[i] = sh[threadIdx.x];
    if (threadIdx.x == SCAN_BLK - 1) g_bsum[blockIdx.x] = sh[SCAN_BLK - 1];
}
__global__ void k_scan2(int NB) {
    __shared__ int sh[256];
    int v = (threadIdx.x < NB) ? g_bsum[threadIdx.x] : 0;
    sh[threadIdx.x] = v;
    __syncthreads();
    for (int d = 1; d < 256; d <<= 1) {
        int t = (threadIdx.x >= d) ? sh[threadIdx.x - d] : 0;
        __syncthreads();
        sh[threadIdx.x] += t;
        __syncthreads();
    }
    g_btop[threadIdx.x] = sh[threadIdx.x] - v;
}

__global__ void k_scatter(const int* __restrict__ e_point,
                          const int* __restrict__ e_new, int E) {
    int i = blockIdx.x * blockDim.x + threadIdx.x;
    if (i < E) {
        int m = e_new[i];
        int base = g_incl[m] - g_cnt[m] + g_btop[m >> 10];
        int pos = base + atomicAdd(&g_cursor[m], 1);
        g_sorted[pos] = make_int2(e_point[i], m);
    }
}

// ---------------------------------------------------------------------------
__device__ __forceinline__ void mma_bf16(float& c0, float& c1, float& c2, float& c3,
                                         unsigned a0, unsigned a1, unsigned a2, unsigned a3,
                                         unsigned b0, unsigned b1) {
    asm volatile("mma.sync.aligned.m16n8k16.row.col.f32.bf16.bf16.f32 "
                 "{%0,%1,%2,%3}, {%4,%5,%6,%7}, {%8,%9}, {%0,%1,%2,%3};"
                 : "+f"(c0), "+f"(c1), "+f"(c2), "+f"(c3)
                 : "r"(a0), "r"(a1), "r"(a2), "r"(a3), "r"(b0), "r"(b1));
}

// SMEM layout. Weights: uint2 (hi,lo), row stride 68 -> bank 8*tg+2*g+const,
// conflict-free per 16-lane phase for 64-bit LDS. Scratch: f32 stride 68.
#define S_W1   0                          // uint2 [24][68]
#define S_W2   (24 * 68)                  // uint2 [32][68]
#define W_TOT  (S_W2 + 32 * 68)           // 3808 uint2 = 7616 words
#define S_B1   (2 * W_TOT)                // f32 word offsets from here
#define S_B2   (S_B1 + 64)
#define S_MM   (S_B2 + 64)                // [64] int
#define S_SC   (S_MM + 64)                // [64][68] f32
#define S_TOT  (S_SC + 64 * 68)           // 11984 + 7616/... words total below
// total 32-bit words = 2*W_TOT + 64 + 64 + 64 + 64*68 = 7616+192+4352 = 12160 -> 48640 B

__global__ __launch_bounds__(128, 4)
void k_main_tc(const float4* __restrict__ bxyz4,
               const float4* __restrict__ feat4,
               const float*  __restrict__ b1, const float* __restrict__ b2,
               const float4* __restrict__ newb4,
               int*          __restrict__ outf,
               int E)
{
    extern __shared__ float sm[];
    uint2* W1s = (uint2*)sm + S_W1;
    uint2* W2s = (uint2*)sm + S_W2;
    float* b1s = sm + S_B1;
    float* b2s = sm + S_B2;
    int*   smm = (int*)(sm + S_MM);
    float* sc  = sm + S_SC;

    int tid  = threadIdx.x;
    int warp = tid >> 5;
    int lane = tid & 31;
    int g    = lane >> 2;
    int tg   = lane & 3;

    // ---- stage weights (once per block) ----
    for (int i = tid; i < 24 * 64; i += 128) {
        int kp = i >> 6, n = i & 63;
        W1s[kp * 68 + n] = g_W1i[i];
    }
    for (int i = tid; i < 32 * 64; i += 128) {
        int kp = i >> 6, n = i & 63;
        W2s[kp * 68 + n] = g_W2i[i];
    }
    if (tid < 64) { b1s[tid] = b1[tid]; b2s[tid] = b2[tid]; }

    for (int tb = 0; tb < TPB; tb++) {
        int base = (blockIdx.x * TPB + tb) * TILE;
        if (base >= E) break;
        __syncthreads();    // prior epilogue done before sc/smm reuse

        // ---- stage 64 edge rows (warp-local: warp w owns rows 16w..16w+15) ----
        {
            int row  = tid >> 1;
            int half = tid & 1;
            int e = base + row;
            float* rp = sc + row * 68;
            if (e < E) {
                int2 em = g_sorted[e];
                int p = em.x, m = em.y;
                const float4* fp = feat4 + (size_t)p * 8;
                if (half == 0) {
                    smm[row] = m;
                    #pragma unroll
                    for (int q = 0; q < 4; q++) ((float4*)rp)[q] = fp[q];
                } else {
                    #pragma unroll
                    for (int q = 4; q < 8; q++) ((float4*)rp)[q] = fp[q];
                    float4 pb = bxyz4[p];
                    float4 nb = newb4[m];
                    ((float4*)rp)[8]  = make_float4(pb.y - nb.y, pb.z - nb.z, pb.w - nb.w, 0.f);
                    ((float4*)rp)[9]  = make_float4(0.f, 0.f, 0.f, 0.f);
                    ((float4*)rp)[10] = make_float4(0.f, 0.f, 0.f, 0.f);
                    ((float4*)rp)[11] = make_float4(0.f, 0.f, 0.f, 0.f);
                }
            } else {
                if (half == 0) {
                    smm[row] = -1;
                    #pragma unroll
                    for (int q = 0; q < 4; q++) ((float4*)rp)[q] = make_float4(0.f,0.f,0.f,0.f);
                } else {
                    #pragma unroll
                    for (int q = 4; q < 12; q++) ((float4*)rp)[q] = make_float4(0.f,0.f,0.f,0.f);
                }
            }
        }
        __syncwarp();

        int ra = warp * 16 + g;

        // ---- layer-2 A fragments, built directly from layer-1 accumulators ----
        unsigned a2h[4][4], a2l[4][4];

        // ===== Layer 1: K=48 (3 kf x 3 split terms); outputs stay in registers =====
        {
            unsigned ahi[3][4], alo[3][4];
            #pragma unroll
            for (int kf = 0; kf < 3; kf++) {
                int k0 = kf * 16 + 2 * tg;
                float2 p0 = *(float2*)&sc[ra * 68 + k0];
                float2 p1 = *(float2*)&sc[(ra + 8) * 68 + k0];
                float2 p2 = *(float2*)&sc[ra * 68 + k0 + 8];
                float2 p3 = *(float2*)&sc[(ra + 8) * 68 + k0 + 8];
                split_pair(p0.x, p0.y, ahi[kf][0], alo[kf][0]);
                split_pair(p1.x, p1.y, ahi[kf][1], alo[kf][1]);
                split_pair(p2.x, p2.y, ahi[kf][2], alo[kf][2]);
                split_pair(p3.x, p3.y, ahi[kf][3], alo[kf][3]);
            }
            #pragma unroll
            for (int nt = 0; nt < 8; nt++) {
                float c0 = 0.f, c1 = 0.f, c2 = 0.f, c3 = 0.f;
                int nb = nt * 8 + g;
                #pragma unroll
                for (int kf = 0; kf < 3; kf++) {
                    uint2 w0 = W1s[(kf * 8 + tg) * 68 + nb];        // (bh0, bl0)
                    uint2 w1 = W1s[(kf * 8 + tg + 4) * 68 + nb];    // (bh1, bl1)
                    mma_bf16(c0, c1, c2, c3, ahi[kf][0], ahi[kf][1], ahi[kf][2], ahi[kf][3], w0.x, w1.x);
                    mma_bf16(c0, c1, c2, c3, alo[kf][0], alo[kf][1], alo[kf][2], alo[kf][3], w0.x, w1.x);
                    mma_bf16(c0, c1, c2, c3, ahi[kf][0], ahi[kf][1], ahi[kf][2], ahi[kf][3], w0.y, w1.y);
                }
                int col = nt * 8 + 2 * tg;
                float v0 = fmaxf(c0 + b1s[col], 0.f);
                float v1 = fmaxf(c1 + b1s[col + 1], 0.f);
                float v2 = fmaxf(c2 + b1s[col], 0.f);
                float v3 = fmaxf(c3 + b1s[col + 1], 0.f);
                // C-frag (rows g/g+8, cols 8nt+2tg) == A-frag of layer2 kf2=nt>>1:
                // nt even -> a0 (row g), a1 (row g+8); nt odd -> a2, a3.
                int kf2 = nt >> 1;
                int ix  = (nt & 1) * 2;
                split_pair(v0, v1, a2h[kf2][ix],     a2l[kf2][ix]);
                split_pair(v2, v3, a2h[kf2][ix + 1], a2l[kf2][ix + 1]);
            }
        }

        // ===== Layer 2: K=64 (4 kf x 3 terms); out -> sc (rows fully consumed above) =====
        {
            #pragma unroll
            for (int nt = 0; nt < 8; nt++) {
                float c0 = 0.f, c1 = 0.f, c2 = 0.f, c3 = 0.f;
                int nb = nt * 8 + g;
                #pragma unroll
                for (int kf = 0; kf < 4; kf++) {
                    uint2 w0 = W2s[(kf * 8 + tg) * 68 + nb];
                    uint2 w1 = W2s[(kf * 8 + tg + 4) * 68 + nb];
                    mma_bf16(c0, c1, c2, c3, a2h[kf][0], a2h[kf][1], a2h[kf][2], a2h[kf][3], w0.x, w1.x);
                    mma_bf16(c0, c1, c2, c3, a2l[kf][0], a2l[kf][1], a2l[kf][2], a2l[kf][3], w0.x, w1.x);
                    mma_bf16(c0, c1, c2, c3, a2h[kf][0], a2h[kf][1], a2h[kf][2], a2h[kf][3], w0.y, w1.y);
                }
                int col = nt * 8 + 2 * tg;
                *(float2*)&sc[ra * 68 + col] =
                    make_float2(fmaxf(c0 + b2s[col], 0.f), fmaxf(c1 + b2s[col + 1], 0.f));
                *(float2*)&sc[(ra + 8) * 68 + col] =
                    make_float2(fmaxf(c2 + b2s[col], 0.f), fmaxf(c3 + b2s[col + 1], 0.f));
            }
        }
        __syncthreads();

        // ---- segment-max over the sorted 64-row tile ----
        {
            int c  = tid & 63;
            int rs = (tid >> 6) * 32;
            float best = 0.f;
            int cur = -1;
            #pragma unroll 1
            for (int r = rs; r < rs + 32; r++) {
                int m = smm[r];
                if (m < 0) break;
                if (m != cur) {
                    if (cur >= 0)
                        atomicMax(&outf[(size_t)cur * 64 + c], __float_as_int(best));
                    cur = m;
                    best = 0.f;
                }
                best = fmaxf(best, sc[r * 68 + c]);
            }
            if (cur >= 0)
                atomicMax(&outf[(size_t)cur * 64 + c], __float_as_int(best));
        }
    }
}

// ---------------------------------------------------------------------------
extern "C" void kernel_launch(void* const* d_in, const int* in_sizes, int n_in,
                              void* d_out, int out_size)
{
    const float* point_bxyz = (const float*)d_in[0];
    const float* point_feat = (const float*)d_in[1];
    const int*   sample_idx = (const int*)  d_in[2];
    const int*   e_point    = (const int*)  d_in[3];
    const int*   e_new      = (const int*)  d_in[4];
    const float* W1         = (const float*)d_in[5];
    const float* b1         = (const float*)d_in[6];
    const float* W2         = (const float*)d_in[7];
    const float* b2         = (const float*)d_in[8];

    float* out = (float*)d_out;
    int M = in_sizes[2];
    int E = in_sizes[3];

    int smem_words = 2 * W_TOT + 64 + 64 + 64 + 64 * 68;
    cudaFuncSetAttribute(k_main_tc, cudaFuncAttributeMaxDynamicSharedMemorySize,
                         smem_words * (int)sizeof(float));

    k_init<<<1024, 256>>>((const float4*)point_bxyz, sample_idx, W1, W2, out, M);
    k_hist<<<(E + 255) / 256, 256>>>(e_new, E);

    int NB = (M + SCAN_BLK - 1) / SCAN_BLK;
    k_scan1<<<NB, SCAN_BLK>>>(M);
    k_scan2<<<1, 256>>>(NB);

    k_scatter<<<(E + 255) / 256, 256>>>(e_point, e_new, E);

    int nblk = (E + TILE * TPB - 1) / (TILE * TPB);
    k_main_tc<<<nblk, 128, smem_words * sizeof(float)>>>(
        (const float4*)point_bxyz, (const float4*)point_feat,
        b1, b2,
        (const float4*)out,
        (int*)(out + 4 * (size_t)M),
        E);
}

// round 10
// speedup vs baseline: 2.3446x; 1.0002x over previous
#include <cuda_runtime.h>

// GraphConvDown: per-edge MLP (35 -> 64 -> 64) + scatter-max onto M sampled points.
// Round 10: same tensor-core main kernel as R9 (bf16 m16n8k16, 3-term split,
// register-chained layers). Preprocessing compressed 5 -> 3 launches:
//   1) k_init_hist : output init + weight split + e_new histogram (one pass)
//   2) k_scan      : single-kernel decoupled-lookback exclusive scan -> g_start
//   3) k_scatter   : counting-sort scatter via g_start + g_cursor
//   4) k_main_tc   : zeroes counters at start (replay-invariant), then MLP+max
//
// Output layout (float32): out[0..4M) = new_bxyz [M,4]; out[4M..4M+64M) = new_feat [M,64]

#define K1 35
#define MAXM 131072
#define MAXE 2000128
#define SCAN_BLK 1024
#define TILE 64
#define TPB 8

// ---------- static scratch ----------
__device__ int      g_cnt[MAXM];
__device__ int      g_start[MAXM];     // exclusive start offset per segment
__device__ int      g_cursor[MAXM];
__device__ unsigned g_state[128];      // lookback scan state (flag in bits 30-31)
__device__ int2     g_sorted[MAXE];
__device__ uint2    g_W1i[24 * 64];    // (hi, lo) bf16x2 pairs, k padded 35->48
__device__ uint2    g_W2i[32 * 64];    // k=64

__device__ __forceinline__ unsigned pack_bf16(float x, float y) {
    unsigned r;
    asm("cvt.rn.bf16x2.f32 %0, %1, %2;" : "=r"(r) : "f"(y), "f"(x));
    return r;
}
__device__ __forceinline__ void split_pair(float x, float y, unsigned& hi, unsigned& lo) {
    hi = pack_bf16(x, y);
    float hx = __uint_as_float(hi << 16);
    float hy = __uint_as_float(hi & 0xffff0000u);
    lo = pack_bf16(x - hx, y - hy);
}

// ---------------------------------------------------------------------------
// 1) init + weight split + histogram (g_cnt/g_cursor/g_state pre-zeroed by the
//    previous execution's k_main_tc; zero at first call via static init).
// ---------------------------------------------------------------------------
__global__ void k_init_hist(const float4* __restrict__ bxyz4,
                            const int* __restrict__ sample_idx,
                            const int* __restrict__ e_new,
                            const float* __restrict__ W1,
                            const float* __restrict__ W2,
                            float* __restrict__ out, int M, int E) {
    int i = blockIdx.x * blockDim.x + threadIdx.x;
    int stride = gridDim.x * blockDim.x;
    float4* ob = (float4*)out;
    for (int j = i; j < M; j += stride)
        ob[j] = bxyz4[sample_idx[j]];
    float4* fz = (float4*)(out + 4 * (size_t)M);
    int tot = M * 16;
    for (int j = i; j < tot; j += stride)
        fz[j] = make_float4(0.f, 0.f, 0.f, 0.f);
    for (int j = i; j < 24 * 64; j += stride) {
        int kp = j >> 6, n = j & 63;
        int k0 = 2 * kp, k1 = 2 * kp + 1;
        float w0 = (k0 < K1) ? W1[k0 * 64 + n] : 0.f;
        float w1 = (k1 < K1) ? W1[k1 * 64 + n] : 0.f;
        unsigned hi, lo;
        split_pair(w0, w1, hi, lo);
        g_W1i[j] = make_uint2(hi, lo);
    }
    for (int j = i; j < 32 * 64; j += stride) {
        int kp = j >> 6, n = j & 63;
        float w0 = W2[(2 * kp) * 64 + n];
        float w1 = W2[(2 * kp + 1) * 64 + n];
        unsigned hi, lo;
        split_pair(w0, w1, hi, lo);
        g_W2i[j] = make_uint2(hi, lo);
    }
    for (int j = i; j < E; j += stride)
        atomicAdd(&g_cnt[e_new[j]], 1);
}

// ---------------------------------------------------------------------------
// 2) decoupled-lookback exclusive scan: g_start[i] = sum_{j<i} g_cnt[j].
//    NB = ceil(M/1024) = 123 blocks — all resident in wave 1, so the spin on
//    lower-indexed blocks cannot deadlock. Flag(2 bits)+value(30 bits) share
//    one word -> single-word atomicity, no fences needed.
// ---------------------------------------------------------------------------
__global__ void k_scan(int M) {
    __shared__ int sh[SCAN_BLK];
    __shared__ int s_prefix;
    int bid = blockIdx.x;
    int tid = threadIdx.x;
    int i = bid * SCAN_BLK + tid;
    int c = (i < M) ? g_cnt[i] : 0;
    sh[tid] = c;
    __syncthreads();
    for (int d = 1; d < SCAN_BLK; d <<= 1) {
        int t = (tid >= d) ? sh[tid - d] : 0;
        __syncthreads();
        sh[tid] += t;
        __syncthreads();
    }
    int incl = sh[tid];
    if (tid == 0) {
        unsigned agg = (unsigned)sh[SCAN_BLK - 1];
        if (bid == 0) {
            atomicExch(&g_state[0], (2u << 30) | agg);
            s_prefix = 0;
        } else {
            atomicExch(&g_state[bid], (1u << 30) | agg);
            unsigned run = 0;
            int j = bid - 1;
            while (true) {
                unsigned s;
                do { s = atomicAdd(&g_state[j], 0u); } while ((s >> 30) == 0u);
                run += s & 0x3fffffffu;
                if ((s >> 30) == 2u) break;
                j--;
            }
            atomicExch(&g_state[bid], (2u << 30) | (run + agg));
            s_prefix = (int)run;
        }
    }
    __syncthreads();
    if (i < M) g_start[i] = s_prefix + incl - c;
}

// ---------------------------------------------------------------------------
// 3) counting-sort scatter
// ---------------------------------------------------------------------------
__global__ void k_scatter(const int* __restrict__ e_point,
                          const int* __restrict__ e_new, int E) {
    int i = blockIdx.x * blockDim.x + threadIdx.x;
    if (i < E) {
        int m = e_new[i];
        int pos = g_start[m] + atomicAdd(&g_cursor[m], 1);
        g_sorted[pos] = make_int2(e_point[i], m);
    }
}

// ---------------------------------------------------------------------------
__device__ __forceinline__ void mma_bf16(float& c0, float& c1, float& c2, float& c3,
                                         unsigned a0, unsigned a1, unsigned a2, unsigned a3,
                                         unsigned b0, unsigned b1) {
    asm volatile("mma.sync.aligned.m16n8k16.row.col.f32.bf16.bf16.f32 "
                 "{%0,%1,%2,%3}, {%4,%5,%6,%7}, {%8,%9}, {%0,%1,%2,%3};"
                 : "+f"(c0), "+f"(c1), "+f"(c2), "+f"(c3)
                 : "r"(a0), "r"(a1), "r"(a2), "r"(a3), "r"(b0), "r"(b1));
}

// SMEM layout. Weights: uint2 (hi,lo), row stride 68 -> conflict-free 64-bit LDS.
#define S_W1   0                          // uint2 [24][68]
#define S_W2   (24 * 68)                  // uint2 [32][68]
#define W_TOT  (S_W2 + 32 * 68)           // 3808 uint2
#define S_B1   (2 * W_TOT)                // f32 word offsets
#define S_B2   (S_B1 + 64)
#define S_MM   (S_B2 + 64)                // [64] int
#define S_SC   (S_MM + 64)                // [64][68] f32
#define SMEM_WORDS (S_SC + 64 * 68)       // 12160 words = 48640 B

// ---------------------------------------------------------------------------
// 4) main tensor-core kernel (R9 math). Zeroes g_cnt/g_cursor/g_state at start
//    (all consumers already ran this execution -> every execution ends clean).
// ---------------------------------------------------------------------------
__global__ __launch_bounds__(128, 4)
void k_main_tc(const float4* __restrict__ bxyz4,
               const float4* __restrict__ feat4,
               const float*  __restrict__ b1, const float* __restrict__ b2,
               const float4* __restrict__ newb4,
               int*          __restrict__ outf,
               int E, int M)
{
    extern __shared__ float sm[];
    uint2* W1s = (uint2*)sm + S_W1;
    uint2* W2s = (uint2*)sm + S_W2;
    float* b1s = sm + S_B1;
    float* b2s = sm + S_B2;
    int*   smm = (int*)(sm + S_MM);
    float* sc  = sm + S_SC;

    int tid  = threadIdx.x;
    int warp = tid >> 5;
    int lane = tid & 31;
    int g    = lane >> 2;
    int tg   = lane & 3;

    // ---- replay-state zeroing (arrays not otherwise read/written by this kernel) ----
    {
        int gt = blockIdx.x * 128 + tid;
        if (gt < M) { g_cnt[gt] = 0; g_cursor[gt] = 0; }
        if (gt < 128) g_state[gt] = 0u;
    }

    // ---- stage weights (once per block) ----
    for (int i = tid; i < 24 * 64; i += 128) {
        int kp = i >> 6, n = i & 63;
        W1s[kp * 68 + n] = g_W1i[i];
    }
    for (int i = tid; i < 32 * 64; i += 128) {
        int kp = i >> 6, n = i & 63;
        W2s[kp * 68 + n] = g_W2i[i];
    }
    if (tid < 64) { b1s[tid] = b1[tid]; b2s[tid] = b2[tid]; }

    for (int tb = 0; tb < TPB; tb++) {
        int base = (blockIdx.x * TPB + tb) * TILE;
        if (base >= E) break;
        __syncthreads();    // prior epilogue done before sc/smm reuse

        // ---- stage 64 edge rows (warp-local rows) ----
        {
            int row  = tid >> 1;
            int half = tid & 1;
            int e = base + row;
            float* rp = sc + row * 68;
            if (e < E) {
                int2 em = g_sorted[e];
                int p = em.x, m = em.y;
                const float4* fp = feat4 + (size_t)p * 8;
                if (half == 0) {
                    smm[row] = m;
                    #pragma unroll
                    for (int q = 0; q < 4; q++) ((float4*)rp)[q] = fp[q];
                } else {
                    #pragma unroll
                    for (int q = 4; q < 8; q++) ((float4*)rp)[q] = fp[q];
                    float4 pb = bxyz4[p];
                    float4 nb = newb4[m];
                    ((float4*)rp)[8]  = make_float4(pb.y - nb.y, pb.z - nb.z, pb.w - nb.w, 0.f);
                    ((float4*)rp)[9]  = make_float4(0.f, 0.f, 0.f, 0.f);
                    ((float4*)rp)[10] = make_float4(0.f, 0.f, 0.f, 0.f);
                    ((float4*)rp)[11] = make_float4(0.f, 0.f, 0.f, 0.f);
                }
            } else {
                if (half == 0) {
                    smm[row] = -1;
                    #pragma unroll
                    for (int q = 0; q < 4; q++) ((float4*)rp)[q] = make_float4(0.f,0.f,0.f,0.f);
                } else {
                    #pragma unroll
                    for (int q = 4; q < 12; q++) ((float4*)rp)[q] = make_float4(0.f,0.f,0.f,0.f);
                }
            }
        }
        __syncwarp();

        int ra = warp * 16 + g;

        // ---- layer-2 A fragments, built directly from layer-1 accumulators ----
        unsigned a2h[4][4], a2l[4][4];

        // ===== Layer 1: K=48 (3 kf x 3 split terms); outputs stay in registers =====
        {
            unsigned ahi[3][4], alo[3][4];
            #pragma unroll
            for (int kf = 0; kf < 3; kf++) {
                int k0 = kf * 16 + 2 * tg;
                float2 p0 = *(float2*)&sc[ra * 68 + k0];
                float2 p1 = *(float2*)&sc[(ra + 8) * 68 + k0];
                float2 p2 = *(float2*)&sc[ra * 68 + k0 + 8];
                float2 p3 = *(float2*)&sc[(ra + 8) * 68 + k0 + 8];
                split_pair(p0.x, p0.y, ahi[kf][0], alo[kf][0]);
                split_pair(p1.x, p1.y, ahi[kf][1], alo[kf][1]);
                split_pair(p2.x, p2.y, ahi[kf][2], alo[kf][2]);
                split_pair(p3.x, p3.y, ahi[kf][3], alo[kf][3]);
            }
            #pragma unroll
            for (int nt = 0; nt < 8; nt++) {
                float c0 = 0.f, c1 = 0.f, c2 = 0.f, c3 = 0.f;
                int nb = nt * 8 + g;
                #pragma unroll
                for (int kf = 0; kf < 3; kf++) {
                    uint2 w0 = W1s[(kf * 8 + tg) * 68 + nb];        // (bh0, bl0)
                    uint2 w1 = W1s[(kf * 8 + tg + 4) * 68 + nb];    // (bh1, bl1)
                    mma_bf16(c0, c1, c2, c3, ahi[kf][0], ahi[kf][1], ahi[kf][2], ahi[kf][3], w0.x, w1.x);
                    mma_bf16(c0, c1, c2, c3, alo[kf][0], alo[kf][1], alo[kf][2], alo[kf][3], w0.x, w1.x);
                    mma_bf16(c0, c1, c2, c3, ahi[kf][0], ahi[kf][1], ahi[kf][2], ahi[kf][3], w0.y, w1.y);
                }
                int col = nt * 8 + 2 * tg;
                float v0 = fmaxf(c0 + b1s[col], 0.f);
                float v1 = fmaxf(c1 + b1s[col + 1], 0.f);
                float v2 = fmaxf(c2 + b1s[col], 0.f);
                float v3 = fmaxf(c3 + b1s[col + 1], 0.f);
                // C-frag (rows g/g+8, cols 8nt+2tg) == layer-2 A-frag kf2=nt>>1
                int kf2 = nt >> 1;
                int ix  = (nt & 1) * 2;
                split_pair(v0, v1, a2h[kf2][ix],     a2l[kf2][ix]);
                split_pair(v2, v3, a2h[kf2][ix + 1], a2l[kf2][ix + 1]);
            }
        }

        // ===== Layer 2: K=64 (4 kf x 3 terms); out -> sc =====
        {
            #pragma unroll
            for (int nt = 0; nt < 8; nt++) {
                float c0 = 0.f, c1 = 0.f, c2 = 0.f, c3 = 0.f;
                int nb = nt * 8 + g;
                #pragma unroll
                for (int kf = 0; kf < 4; kf++) {
                    uint2 w0 = W2s[(kf * 8 + tg) * 68 + nb];
                    uint2 w1 = W2s[(kf * 8 + tg + 4) * 68 + nb];
                    mma_bf16(c0, c1, c2, c3, a2h[kf][0], a2h[kf][1], a2h[kf][2], a2h[kf][3], w0.x, w1.x);
                    mma_bf16(c0, c1, c2, c3, a2l[kf][0], a2l[kf][1], a2l[kf][2], a2l[kf][3], w0.x, w1.x);
                    mma_bf16(c0, c1, c2, c3, a2h[kf][0], a2h[kf][1], a2h[kf][2], a2h[kf][3], w0.y, w1.y);
                }
                int col = nt * 8 + 2 * tg;
                *(float2*)&sc[ra * 68 + col] =
                    make_float2(fmaxf(c0 + b2s[col], 0.f), fmaxf(c1 + b2s[col + 1], 0.f));
                *(float2*)&sc[(ra + 8) * 68 + col] =
                    make_float2(fmaxf(c2 + b2s[col], 0.f), fmaxf(c3 + b2s[col + 1], 0.f));
            }
        }
        __syncthreads();

        // ---- segment-max over the sorted 64-row tile ----
        {
            int c  = tid & 63;
            int rs = (tid >> 6) * 32;
            float best = 0.f;
            int cur = -1;
            #pragma unroll 1
            for (int r = rs; r < rs + 32; r++) {
                int m = smm[r];
                if (m < 0) break;
                if (m != cur) {
                    if (cur >= 0)
                        atomicMax(&outf[(size_t)cur * 64 + c], __float_as_int(best));
                    cur = m;
                    best = 0.f;
                }
                best = fmaxf(best, sc[r * 68 + c]);
            }
            if (cur >= 0)
                atomicMax(&outf[(size_t)cur * 64 + c], __float_as_int(best));
        }
    }
}

// ---------------------------------------------------------------------------
extern "C" void kernel_launch(void* const* d_in, const int* in_sizes, int n_in,
                              void* d_out, int out_size)
{
    const float* point_bxyz = (const float*)d_in[0];
    const float* point_feat = (const float*)d_in[1];
    const int*   sample_idx = (const int*)  d_in[2];
    const int*   e_point    = (const int*)  d_in[3];
    const int*   e_new      = (const int*)  d_in[4];
    const float* W1         = (const float*)d_in[5];
    const float* b1         = (const float*)d_in[6];
    const float* W2         = (const float*)d_in[7];
    const float* b2         = (const float*)d_in[8];

    float* out = (float*)d_out;
    int M = in_sizes[2];
    int E = in_sizes[3];

    cudaFuncSetAttribute(k_main_tc, cudaFuncAttributeMaxDynamicSharedMemorySize,
                         SMEM_WORDS * (int)sizeof(float));

    k_init_hist<<<2048, 256>>>((const float4*)point_bxyz, sample_idx, e_new,
                               W1, W2, out, M, E);

    int NB = (M + SCAN_BLK - 1) / SCAN_BLK;   // 123 for M=125000 (<=128)
    k_scan<<<NB, SCAN_BLK>>>(M);

    k_scatter<<<(E + 255) / 256, 256>>>(e_point, e_new, E);

    int nblk = (E + TILE * TPB - 1) / (TILE * TPB);
    k_main_tc<<<nblk, 128, SMEM_WORDS * sizeof(float)>>>(
        (const float4*)point_bxyz, (const float4*)point_feat,
        b1, b2,
        (const float4*)out,
        (int*)(out + 4 * (size_t)M),
        E, M);
}

// round 11
// speedup vs baseline: 2.9303x; 1.2498x over previous
#include <cuda_runtime.h>

// GraphConvDown: per-edge MLP (35 -> 64 -> 64) + scatter-max onto M sampled points.
// Round 11: same math as R9/R10 (bf16 m16n8k16, 3-term split, register-chained
// layers). Occupancy fix: 256-thread blocks on 128-edge tiles -> 3 blocks/SM
// (24 warps, occ 37.5% vs 24.2%), weights amortized over 8 warps; epilogue made
// unrollable (no break) so its 32 LDS pipeline instead of serializing.
//
// Output layout (float32): out[0..4M) = new_bxyz [M,4]; out[4M..4M+64M) = new_feat [M,64]

#define K1 35
#define MAXM 131072
#define MAXE 2000128
#define SCAN_BLK 1024
#define TILE 128
#define TPB 8
#define THREADS 256

// ---------- static scratch ----------
__device__ int      g_cnt[MAXM];
__device__ int      g_start[MAXM];
__device__ int      g_cursor[MAXM];
__device__ unsigned g_state[128];
__device__ int2     g_sorted[MAXE];
__device__ uint2    g_W1i[24 * 64];    // (hi, lo) bf16x2 pairs, k padded 35->48
__device__ uint2    g_W2i[32 * 64];    // k=64

__device__ __forceinline__ unsigned pack_bf16(float x, float y) {
    unsigned r;
    asm("cvt.rn.bf16x2.f32 %0, %1, %2;" : "=r"(r) : "f"(y), "f"(x));
    return r;
}
__device__ __forceinline__ void split_pair(float x, float y, unsigned& hi, unsigned& lo) {
    hi = pack_bf16(x, y);
    float hx = __uint_as_float(hi << 16);
    float hy = __uint_as_float(hi & 0xffff0000u);
    lo = pack_bf16(x - hx, y - hy);
}

// ---------------------------------------------------------------------------
// 1) init + weight split + histogram
// ---------------------------------------------------------------------------
__global__ void k_init_hist(const float4* __restrict__ bxyz4,
                            const int* __restrict__ sample_idx,
                            const int* __restrict__ e_new,
                            const float* __restrict__ W1,
                            const float* __restrict__ W2,
                            float* __restrict__ out, int M, int E) {
    int i = blockIdx.x * blockDim.x + threadIdx.x;
    int stride = gridDim.x * blockDim.x;
    float4* ob = (float4*)out;
    for (int j = i; j < M; j += stride)
        ob[j] = bxyz4[sample_idx[j]];
    float4* fz = (float4*)(out + 4 * (size_t)M);
    int tot = M * 16;
    for (int j = i; j < tot; j += stride)
        fz[j] = make_float4(0.f, 0.f, 0.f, 0.f);
    for (int j = i; j < 24 * 64; j += stride) {
        int kp = j >> 6, n = j & 63;
        int k0 = 2 * kp, k1 = 2 * kp + 1;
        float w0 = (k0 < K1) ? W1[k0 * 64 + n] : 0.f;
        float w1 = (k1 < K1) ? W1[k1 * 64 + n] : 0.f;
        unsigned hi, lo;
        split_pair(w0, w1, hi, lo);
        g_W1i[j] = make_uint2(hi, lo);
    }
    for (int j = i; j < 32 * 64; j += stride) {
        int kp = j >> 6, n = j & 63;
        float w0 = W2[(2 * kp) * 64 + n];
        float w1 = W2[(2 * kp + 1) * 64 + n];
        unsigned hi, lo;
        split_pair(w0, w1, hi, lo);
        g_W2i[j] = make_uint2(hi, lo);
    }
    for (int j = i; j < E; j += stride)
        atomicAdd(&g_cnt[e_new[j]], 1);
}

// ---------------------------------------------------------------------------
// 2) decoupled-lookback exclusive scan (123 blocks, single wave, no deadlock)
// ---------------------------------------------------------------------------
__global__ void k_scan(int M) {
    __shared__ int sh[SCAN_BLK];
    __shared__ int s_prefix;
    int bid = blockIdx.x;
    int tid = threadIdx.x;
    int i = bid * SCAN_BLK + tid;
    int c = (i < M) ? g_cnt[i] : 0;
    sh[tid] = c;
    __syncthreads();
    for (int d = 1; d < SCAN_BLK; d <<= 1) {
        int t = (tid >= d) ? sh[tid - d] : 0;
        __syncthreads();
        sh[tid] += t;
        __syncthreads();
    }
    int incl = sh[tid];
    if (tid == 0) {
        unsigned agg = (unsigned)sh[SCAN_BLK - 1];
        if (bid == 0) {
            atomicExch(&g_state[0], (2u << 30) | agg);
            s_prefix = 0;
        } else {
            atomicExch(&g_state[bid], (1u << 30) | agg);
            unsigned run = 0;
            int j = bid - 1;
            while (true) {
                unsigned s;
                do { s = atomicAdd(&g_state[j], 0u); } while ((s >> 30) == 0u);
                run += s & 0x3fffffffu;
                if ((s >> 30) == 2u) break;
                j--;
            }
            atomicExch(&g_state[bid], (2u << 30) | (run + agg));
            s_prefix = (int)run;
        }
    }
    __syncthreads();
    if (i < M) g_start[i] = s_prefix + incl - c;
}

// ---------------------------------------------------------------------------
// 3) counting-sort scatter
// ---------------------------------------------------------------------------
__global__ void k_scatter(const int* __restrict__ e_point,
                          const int* __restrict__ e_new, int E) {
    int i = blockIdx.x * blockDim.x + threadIdx.x;
    if (i < E) {
        int m = e_new[i];
        int pos = g_start[m] + atomicAdd(&g_cursor[m], 1);
        g_sorted[pos] = make_int2(e_point[i], m);
    }
}

// ---------------------------------------------------------------------------
__device__ __forceinline__ void mma_bf16(float& c0, float& c1, float& c2, float& c3,
                                         unsigned a0, unsigned a1, unsigned a2, unsigned a3,
                                         unsigned b0, unsigned b1) {
    asm volatile("mma.sync.aligned.m16n8k16.row.col.f32.bf16.bf16.f32 "
                 "{%0,%1,%2,%3}, {%4,%5,%6,%7}, {%8,%9}, {%0,%1,%2,%3};"
                 : "+f"(c0), "+f"(c1), "+f"(c2), "+f"(c3)
                 : "r"(a0), "r"(a1), "r"(a2), "r"(a3), "r"(b0), "r"(b1));
}

// SMEM layout (32-bit word offsets).
#define S_W1   0                          // uint2 [24][68]
#define S_W2   (24 * 68)                  // uint2 [32][68]
#define W_TOT  (S_W2 + 32 * 68)           // 3808 uint2
#define S_B1   (2 * W_TOT)                // f32 words
#define S_B2   (S_B1 + 64)
#define S_MM   (S_B2 + 64)                // [128] int
#define S_SC   (S_MM + 128)               // [128][68] f32
#define SMEM_WORDS (S_SC + 128 * 68)      // 16576 words = 66304 B -> 3 blocks/SM

// ---------------------------------------------------------------------------
// 4) main tensor-core kernel: 256 threads (8 warps), 128-edge tiles.
// ---------------------------------------------------------------------------
__global__ __launch_bounds__(THREADS, 3)
void k_main_tc(const float4* __restrict__ bxyz4,
               const float4* __restrict__ feat4,
               const float*  __restrict__ b1, const float* __restrict__ b2,
               const float4* __restrict__ newb4,
               int*          __restrict__ outf,
               int E, int M)
{
    extern __shared__ float sm[];
    uint2* W1s = (uint2*)sm + S_W1;
    uint2* W2s = (uint2*)sm + S_W2;
    float* b1s = sm + S_B1;
    float* b2s = sm + S_B2;
    int*   smm = (int*)(sm + S_MM);
    float* sc  = sm + S_SC;

    int tid  = threadIdx.x;
    int warp = tid >> 5;
    int lane = tid & 31;
    int g    = lane >> 2;
    int tg   = lane & 3;

    // ---- replay-state zeroing (grid 1954 x 256 covers M) ----
    {
        int gt = blockIdx.x * THREADS + tid;
        if (gt < M) { g_cnt[gt] = 0; g_cursor[gt] = 0; }
        if (gt < 128) g_state[gt] = 0u;
    }

    // ---- stage weights (once per block, amortized over 8 warps) ----
    for (int i = tid; i < 24 * 64; i += THREADS) {
        int kp = i >> 6, n = i & 63;
        W1s[kp * 68 + n] = g_W1i[i];
    }
    for (int i = tid; i < 32 * 64; i += THREADS) {
        int kp = i >> 6, n = i & 63;
        W2s[kp * 68 + n] = g_W2i[i];
    }
    if (tid < 64) { b1s[tid] = b1[tid]; b2s[tid] = b2[tid]; }

    for (int tb = 0; tb < TPB; tb++) {
        int base = (blockIdx.x * TPB + tb) * TILE;
        if (base >= E) break;
        __syncthreads();    // prior epilogue done before sc/smm reuse

        // ---- stage 128 edge rows, 2 threads per row (warp-local rows) ----
        {
            int row  = tid >> 1;
            int half = tid & 1;
            int e = base + row;
            float* rp = sc + row * 68;
            if (e < E) {
                int2 em = g_sorted[e];
                int p = em.x, m = em.y;
                const float4* fp = feat4 + (size_t)p * 8;
                if (half == 0) {
                    smm[row] = m;
                    #pragma unroll
                    for (int q = 0; q < 4; q++) ((float4*)rp)[q] = fp[q];
                } else {
                    #pragma unroll
                    for (int q = 4; q < 8; q++) ((float4*)rp)[q] = fp[q];
                    float4 pb = bxyz4[p];
                    float4 nb = newb4[m];
                    ((float4*)rp)[8]  = make_float4(pb.y - nb.y, pb.z - nb.z, pb.w - nb.w, 0.f);
                    ((float4*)rp)[9]  = make_float4(0.f, 0.f, 0.f, 0.f);
                    ((float4*)rp)[10] = make_float4(0.f, 0.f, 0.f, 0.f);
                    ((float4*)rp)[11] = make_float4(0.f, 0.f, 0.f, 0.f);
                }
            } else {
                if (half == 0) {
                    smm[row] = -1;
                    #pragma unroll
                    for (int q = 0; q < 4; q++) ((float4*)rp)[q] = make_float4(0.f,0.f,0.f,0.f);
                } else {
                    #pragma unroll
                    for (int q = 4; q < 12; q++) ((float4*)rp)[q] = make_float4(0.f,0.f,0.f,0.f);
                }
            }
        }
        __syncwarp();       // staging rows and compute rows are warp-local

        int ra = warp * 16 + g;

        // ---- layer-2 A fragments, built directly from layer-1 accumulators ----
        unsigned a2h[4][4], a2l[4][4];

        // ===== Layer 1: K=48 (3 kf x 3 split terms) =====
        {
            unsigned ahi[3][4], alo[3][4];
            #pragma unroll
            for (int kf = 0; kf < 3; kf++) {
                int k0 = kf * 16 + 2 * tg;
                float2 p0 = *(float2*)&sc[ra * 68 + k0];
                float2 p1 = *(float2*)&sc[(ra + 8) * 68 + k0];
                float2 p2 = *(float2*)&sc[ra * 68 + k0 + 8];
                float2 p3 = *(float2*)&sc[(ra + 8) * 68 + k0 + 8];
                split_pair(p0.x, p0.y, ahi[kf][0], alo[kf][0]);
                split_pair(p1.x, p1.y, ahi[kf][1], alo[kf][1]);
                split_pair(p2.x, p2.y, ahi[kf][2], alo[kf][2]);
                split_pair(p3.x, p3.y, ahi[kf][3], alo[kf][3]);
            }
            #pragma unroll
            for (int nt = 0; nt < 8; nt++) {
                float c0 = 0.f, c1 = 0.f, c2 = 0.f, c3 = 0.f;
                int nb = nt * 8 + g;
                #pragma unroll
                for (int kf = 0; kf < 3; kf++) {
                    uint2 w0 = W1s[(kf * 8 + tg) * 68 + nb];        // (bh0, bl0)
                    uint2 w1 = W1s[(kf * 8 + tg + 4) * 68 + nb];    // (bh1, bl1)
                    mma_bf16(c0, c1, c2, c3, ahi[kf][0], ahi[kf][1], ahi[kf][2], ahi[kf][3], w0.x, w1.x);
                    mma_bf16(c0, c1, c2, c3, alo[kf][0], alo[kf][1], alo[kf][2], alo[kf][3], w0.x, w1.x);
                    mma_bf16(c0, c1, c2, c3, ahi[kf][0], ahi[kf][1], ahi[kf][2], ahi[kf][3], w0.y, w1.y);
                }
                int col = nt * 8 + 2 * tg;
                float v0 = fmaxf(c0 + b1s[col], 0.f);
                float v1 = fmaxf(c1 + b1s[col + 1], 0.f);
                float v2 = fmaxf(c2 + b1s[col], 0.f);
                float v3 = fmaxf(c3 + b1s[col + 1], 0.f);
                // C-frag (rows g/g+8, cols 8nt+2tg) == layer-2 A-frag kf2=nt>>1
                int kf2 = nt >> 1;
                int ix  = (nt & 1) * 2;
                split_pair(v0, v1, a2h[kf2][ix],     a2l[kf2][ix]);
                split_pair(v2, v3, a2h[kf2][ix + 1], a2l[kf2][ix + 1]);
            }
        }

        // ===== Layer 2: K=64 (4 kf x 3 terms); out -> sc =====
        {
            #pragma unroll
            for (int nt = 0; nt < 8; nt++) {
                float c0 = 0.f, c1 = 0.f, c2 = 0.f, c3 = 0.f;
                int nb = nt * 8 + g;
                #pragma unroll
                for (int kf = 0; kf < 4; kf++) {
                    uint2 w0 = W2s[(kf * 8 + tg) * 68 + nb];
                    uint2 w1 = W2s[(kf * 8 + tg + 4) * 68 + nb];
                    mma_bf16(c0, c1, c2, c3, a2h[kf][0], a2h[kf][1], a2h[kf][2], a2h[kf][3], w0.x, w1.x);
                    mma_bf16(c0, c1, c2, c3, a2l[kf][0], a2l[kf][1], a2l[kf][2], a2l[kf][3], w0.x, w1.x);
                    mma_bf16(c0, c1, c2, c3, a2h[kf][0], a2h[kf][1], a2h[kf][2], a2h[kf][3], w0.y, w1.y);
                }
                int col = nt * 8 + 2 * tg;
                *(float2*)&sc[ra * 68 + col] =
                    make_float2(fmaxf(c0 + b2s[col], 0.f), fmaxf(c1 + b2s[col + 1], 0.f));
                *(float2*)&sc[(ra + 8) * 68 + col] =
                    make_float2(fmaxf(c2 + b2s[col], 0.f), fmaxf(c3 + b2s[col + 1], 0.f));
            }
        }
        __syncthreads();

        // ---- segment-max over the sorted 128-row tile (unrollable: no break) ----
        {
            int c  = tid & 63;
            int rs = (tid >> 6) * 32;     // 4 row-groups x 32 rows
            float best = 0.f;
            int cur = -1;
            #pragma unroll 8
            for (int r = rs; r < rs + 32; r++) {
                int m = smm[r];
                float v = sc[r * 68 + c];
                if (m != cur) {
                    if (cur >= 0)
                        atomicMax(&outf[(size_t)cur * 64 + c], __float_as_int(best));
                    cur = m;
                    best = 0.f;
                }
                best = fmaxf(best, v);    // cur==-1 rows accumulate but never flush
            }
            if (cur >= 0)
                atomicMax(&outf[(size_t)cur * 64 + c], __float_as_int(best));
        }
    }
}

// ---------------------------------------------------------------------------
extern "C" void kernel_launch(void* const* d_in, const int* in_sizes, int n_in,
                              void* d_out, int out_size)
{
    const float* point_bxyz = (const float*)d_in[0];
    const float* point_feat = (const float*)d_in[1];
    const int*   sample_idx = (const int*)  d_in[2];
    const int*   e_point    = (const int*)  d_in[3];
    const int*   e_new      = (const int*)  d_in[4];
    const float* W1         = (const float*)d_in[5];
    const float* b1         = (const float*)d_in[6];
    const float* W2         = (const float*)d_in[7];
    const float* b2         = (const float*)d_in[8];

    float* out = (float*)d_out;
    int M = in_sizes[2];
    int E = in_sizes[3];

    cudaFuncSetAttribute(k_main_tc, cudaFuncAttributeMaxDynamicSharedMemorySize,
                         SMEM_WORDS * (int)sizeof(float));

    k_init_hist<<<2048, 256>>>((const float4*)point_bxyz, sample_idx, e_new,
                               W1, W2, out, M, E);

    int NB = (M + SCAN_BLK - 1) / SCAN_BLK;
    k_scan<<<NB, SCAN_BLK>>>(M);

    k_scatter<<<(E + 255) / 256, 256>>>(e_point, e_new, E);

    int nblk = (E + TILE * TPB - 1) / (TILE * TPB);
    k_main_tc<<<nblk, THREADS, SMEM_WORDS * sizeof(float)>>>(
        (const float4*)point_bxyz, (const float4*)point_feat,
        b1, b2,
        (const float4*)out,
        (int*)(out + 4 * (size_t)M),
        E, M);
}